// round 9
// baseline (speedup 1.0000x reference)
#include <cuda_runtime.h>
#include <cuda_bf16.h>
#include <math.h>
#include <stdint.h>

// ---------------- problem constants ----------------
#define SEQ      2048
#define HIDDEN   2048
#define N_HEADS  32
#define N_KV     8
#define HEAD_DIM 64
#define KV_DIM   (N_KV * HEAD_DIM)   // 512

// ---------------- scratch ----------------
__device__ float g_q[SEQ * HIDDEN];
__device__ float g_k[SEQ * KV_DIM];
__device__ float g_v[SEQ * KV_DIM];

// fragment-staged operands (tf32 bits). Tile = 2048 words (8KB).
__device__ uint32_t g_xa[(SEQ / 128) * (HIDDEN / 16) * 2048];
__device__ uint32_t g_wq[(HIDDEN / 16) * (HIDDEN / 128) * 2048];
__device__ uint32_t g_wk[(HIDDEN / 16) * (KV_DIM / 128) * 2048];
__device__ uint32_t g_wv[(HIDDEN / 16) * (KV_DIM / 128) * 2048];
__device__ uint32_t g_wo[(HIDDEN / 16) * (HIDDEN / 128) * 2048];
__device__ uint32_t g_oa[(SEQ / 128) * (HIDDEN / 16) * 2048];

__device__ __forceinline__ uint32_t f2tf32(float x) {
    uint32_t r;
    asm("cvt.rna.tf32.f32 %0, %1;" : "=r"(r) : "f"(x));
    return r;
}

__device__ __forceinline__ void mma_tf32(float c[4], const uint32_t a[4], const uint32_t b[2]) {
    asm volatile(
        "mma.sync.aligned.m16n8k8.row.col.f32.tf32.tf32.f32 "
        "{%0,%1,%2,%3},{%4,%5,%6,%7},{%8,%9},{%0,%1,%2,%3};"
        : "+f"(c[0]), "+f"(c[1]), "+f"(c[2]), "+f"(c[3])
        : "r"(a[0]), "r"(a[1]), "r"(a[2]), "r"(a[3]), "r"(b[0]), "r"(b[1]));
}

__device__ __forceinline__ uint32_t smem_u32(const void* p) {
    return (uint32_t)__cvta_generic_to_shared(p);
}
__device__ __forceinline__ void cp_async16(void* smem, const void* gmem) {
    asm volatile("cp.async.cg.shared.global [%0], [%1], 16;"
                 :: "r"(smem_u32(smem)), "l"(gmem));
}
#define CP_COMMIT() asm volatile("cp.async.commit_group;")
#define CP_WAIT2()  asm volatile("cp.async.wait_group 2;")

// ---------------- fragment scatter maps ------------------------------------
__device__ __forceinline__ void stage_a(uint32_t* dst, float4 v, int lin) {
    const int arow = lin >> 2;
    const int cbase = (lin & 3) * 4;
    float vv[4] = {v.x, v.y, v.z, v.w};
#pragma unroll
    for (int u = 0; u < 4; u++) {
        int j  = cbase + u;
        int mt = arow >> 4, rr = arow & 15;
        int ks = j >> 3,    cc = j & 7;
        int t   = (rr & 7) * 4 + (cc & 3);
        int reg = (rr >> 3) + 2 * (cc >> 2);
        dst[((mt * 2 + ks) * 32 + t) * 4 + reg] = f2tf32(vv[u]);
    }
}
__device__ __forceinline__ void stage_b(uint32_t* dst, float4 v, int lin) {
    const int brow = lin >> 5;
    const int cbase = (lin & 31) * 4;
    float vv[4] = {v.x, v.y, v.z, v.w};
#pragma unroll
    for (int u = 0; u < 4; u++) {
        int j  = cbase + u;
        int nt = j >> 3, cc = j & 7;
        int ks = brow >> 3, kk = brow & 7;
        int t   = cc * 4 + (kk & 3);
        int reg = kk >> 2;
        dst[((nt * 2 + ks) * 32 + t) * 2 + reg] = f2tf32(vv[u]);
    }
}

// ---------------- combined shuffle (all operands, one launch) ---------------
__device__ __forceinline__ void shuffle_a_body(
    const float* __restrict__ A, uint32_t* __restrict__ Af,
    int K, int ktp, int by, uint32_t* buf)
{
    const int kt0 = ktp * 2;
    const int Kt = K / 16;
    const int tid = threadIdx.x;
    const int row0 = tid >> 2, c40 = (tid & 3) * 4;
    const int lin1 = 256 + tid;
    const int row1 = lin1 >> 2, c41 = (lin1 & 3) * 4;
    const float* Ab = A + (size_t)(by * 128) * K;

    float4 v[2][2];
#pragma unroll
    for (int t = 0; t < 2; t++) {
        const float* base = Ab + (kt0 + t) * 16;
        v[t][0] = *(const float4*)(base + (size_t)row0 * K + c40);
        v[t][1] = *(const float4*)(base + (size_t)row1 * K + c41);
    }
#pragma unroll
    for (int t = 0; t < 2; t++) {
        stage_a(buf + t * 2048, v[t][0], tid);
        stage_a(buf + t * 2048, v[t][1], lin1);
    }
    __syncthreads();
#pragma unroll
    for (int t = 0; t < 2; t++) {
        uint32_t* dst = Af + ((size_t)by * Kt + kt0 + t) * 2048;
        *(uint4*)(dst + tid * 4)        = *(const uint4*)(buf + t * 2048 + tid * 4);
        *(uint4*)(dst + 1024 + tid * 4) = *(const uint4*)(buf + t * 2048 + 1024 + tid * 4);
    }
}

__device__ __forceinline__ void shuffle_b_body(
    const float* __restrict__ B, uint32_t* __restrict__ Bf,
    int K, int N, int bx, int ktp, uint32_t* buf)
{
    const int kt0 = ktp * 2;
    const int NB = N / 128;
    const int tid = threadIdx.x;
    const int brow0 = tid >> 5, c40 = (tid & 31) * 4;
    const int lin1 = 256 + tid;
    const int brow1 = lin1 >> 5, c41 = (lin1 & 31) * 4;

    float4 v[2][2];
#pragma unroll
    for (int t = 0; t < 2; t++) {
        const float* Bb = B + (size_t)((kt0 + t) * 16) * N + bx * 128;
        v[t][0] = *(const float4*)(Bb + (size_t)brow0 * N + c40);
        v[t][1] = *(const float4*)(Bb + (size_t)brow1 * N + c41);
    }
#pragma unroll
    for (int t = 0; t < 2; t++) {
        stage_b(buf + t * 2048, v[t][0], tid);
        stage_b(buf + t * 2048, v[t][1], lin1);
    }
    __syncthreads();
#pragma unroll
    for (int t = 0; t < 2; t++) {
        uint32_t* dst = Bf + ((size_t)(kt0 + t) * NB + bx) * 2048;
        *(uint4*)(dst + tid * 4)        = *(const uint4*)(buf + t * 2048 + tid * 4);
        *(uint4*)(dst + 1024 + tid * 4) = *(const uint4*)(buf + t * 2048 + 1024 + tid * 4);
    }
}

__global__ __launch_bounds__(256) void shuffle_all_kernel(
    const float* __restrict__ x,
    const float* __restrict__ Wq, const float* __restrict__ Wk,
    const float* __restrict__ Wv, const float* __restrict__ Wo,
    uint32_t* __restrict__ xa, uint32_t* __restrict__ wq,
    uint32_t* __restrict__ wk, uint32_t* __restrict__ wv,
    uint32_t* __restrict__ wo)
{
    __shared__ __align__(16) uint32_t buf[2 * 2048];
    int b = blockIdx.x;
    if (b < 1024) {
        shuffle_a_body(x, xa, HIDDEN, b & 63, b >> 6, buf);
    } else if (b < 2048) {
        b -= 1024;
        shuffle_b_body(Wq, wq, HIDDEN, HIDDEN, b & 15, b >> 4, buf);
    } else if (b < 2304) {
        b -= 2048;
        shuffle_b_body(Wk, wk, HIDDEN, KV_DIM, b & 3, b >> 2, buf);
    } else if (b < 2560) {
        b -= 2304;
        shuffle_b_body(Wv, wv, HIDDEN, KV_DIM, b & 3, b >> 2, buf);
    } else {
        b -= 2560;
        shuffle_b_body(Wo, wo, HIDDEN, HIDDEN, b & 15, b >> 4, buf);
    }
}

// ---------------- GEMM core: 4-stage cp.async, 1 barrier/iter ---------------
__device__ __forceinline__ void gemm_core(
    const uint32_t* __restrict__ Abase,
    const uint32_t* __restrict__ Bf,
    int Kt, int NB, int bxl,
    const float* __restrict__ bias, float* __restrict__ C, int N,
    int by, uint32_t* As, uint32_t* Bs)
{
    const int tid  = threadIdx.x;
    const int lane = tid & 31;
    const int wid  = tid >> 5;
    const int warp_m = wid >> 2;
    const int warp_n = wid & 3;

    float c[4][4][4];
#pragma unroll
    for (int i = 0; i < 4; i++)
#pragma unroll
        for (int j = 0; j < 4; j++)
#pragma unroll
            for (int r = 0; r < 4; r++) c[i][j][r] = 0.f;

    const int o0 = tid * 4;
    const int o1 = 1024 + tid * 4;

#define G_ISSUE(kt_, s_)                                                     \
    do {                                                                     \
        if ((kt_) < Kt) {                                                    \
            const uint32_t* ag = Abase + (size_t)(kt_) * 2048;               \
            const uint32_t* bg = Bf + ((size_t)(kt_) * NB + bxl) * 2048;     \
            cp_async16(&As[(s_) * 2048 + o0], ag + o0);                      \
            cp_async16(&As[(s_) * 2048 + o1], ag + o1);                      \
            cp_async16(&Bs[(s_) * 2048 + o0], bg + o0);                      \
            cp_async16(&Bs[(s_) * 2048 + o1], bg + o1);                      \
        }                                                                    \
        CP_COMMIT();                                                         \
    } while (0)

    G_ISSUE(0, 0);
    G_ISSUE(1, 1);
    G_ISSUE(2, 2);

    for (int kt = 0; kt < Kt; kt++) {
        const int s = kt & 3;
        CP_WAIT2();
        __syncthreads();
        G_ISSUE(kt + 3, (kt + 3) & 3);

        const uint32_t* Ass = &As[s * 2048];
        const uint32_t* Bss = &Bs[s * 2048];
#pragma unroll
        for (int ks = 0; ks < 2; ks++) {
            uint4 a[4];
            uint2 b[4];
#pragma unroll
            for (int mt = 0; mt < 4; mt++)
                a[mt] = *(const uint4*)&Ass[(((warp_m * 4 + mt) * 2 + ks) * 32 + lane) * 4];
#pragma unroll
            for (int nt = 0; nt < 4; nt++)
                b[nt] = *(const uint2*)&Bss[(((warp_n * 4 + nt) * 2 + ks) * 32 + lane) * 2];
#pragma unroll
            for (int mt = 0; mt < 4; mt++)
#pragma unroll
                for (int nt = 0; nt < 4; nt++) {
                    uint32_t ar[4] = {a[mt].x, a[mt].y, a[mt].z, a[mt].w};
                    uint32_t br[2] = {b[nt].x, b[nt].y};
                    mma_tf32(c[mt][nt], ar, br);
                }
        }
    }
#undef G_ISSUE

#pragma unroll
    for (int mt = 0; mt < 4; mt++) {
        int gr = by * 128 + warp_m * 64 + mt * 16 + (lane >> 2);
#pragma unroll
        for (int nt = 0; nt < 4; nt++) {
            int gc = bxl * 128 + warp_n * 32 + nt * 8 + (lane & 3) * 2;
            float b0 = bias[gc], b1 = bias[gc + 1];
            float2 r0 = {c[mt][nt][0] + b0, c[mt][nt][1] + b1};
            float2 r1 = {c[mt][nt][2] + b0, c[mt][nt][3] + b1};
            *(float2*)(C + (size_t)gr * N + gc) = r0;
            *(float2*)(C + (size_t)(gr + 8) * N + gc) = r1;
        }
    }
}

__global__ __launch_bounds__(256) void tf32_gemm_qkv(
    const uint32_t* __restrict__ Af,
    const uint32_t* __restrict__ Bq, const uint32_t* __restrict__ Bk,
    const uint32_t* __restrict__ Bv,
    const float* __restrict__ bq, const float* __restrict__ bk,
    const float* __restrict__ bv,
    float* __restrict__ cq, float* __restrict__ ck, float* __restrict__ cv)
{
    extern __shared__ __align__(16) uint32_t smem[];
    uint32_t* As = smem;
    uint32_t* Bs = smem + 4 * 2048;

    const int bx = blockIdx.x;
    const int by = blockIdx.y;
    const int Kt = HIDDEN / 16;

    const uint32_t* Bf;
    const float* bias;
    float* C;
    int N, NB, bxl;
    if (bx < 16)      { Bf = Bq; bias = bq; C = cq; N = HIDDEN; NB = 16; bxl = bx; }
    else if (bx < 20) { Bf = Bk; bias = bk; C = ck; N = KV_DIM; NB = 4;  bxl = bx - 16; }
    else              { Bf = Bv; bias = bv; C = cv; N = KV_DIM; NB = 4;  bxl = bx - 20; }

    gemm_core(Af + (size_t)by * Kt * 2048, Bf, Kt, NB, bxl, bias, C, N, by, As, Bs);
}

__global__ __launch_bounds__(256) void tf32_gemm_staged(
    const uint32_t* __restrict__ Af, const uint32_t* __restrict__ Bf,
    const float* __restrict__ bias, float* __restrict__ C,
    int M, int N, int K)
{
    extern __shared__ __align__(16) uint32_t smem[];
    uint32_t* As = smem;
    uint32_t* Bs = smem + 4 * 2048;
    const int Kt = K / 16;
    gemm_core(Af + (size_t)blockIdx.y * Kt * 2048, Bf, Kt, N / 128, blockIdx.x,
              bias, C, N, blockIdx.y, As, Bs);
}

// ---------------- fused per-head LayerNorm + RoPE (q and k, one launch) -----
__global__ void ln_rope_all(float* __restrict__ qb_, float* __restrict__ kb_,
                            const float* __restrict__ q_g, const float* __restrict__ q_b,
                            const float* __restrict__ k_g, const float* __restrict__ k_b)
{
    int row = blockIdx.x * blockDim.y + threadIdx.y;
    const int QROWS = SEQ * N_HEADS;
    const int TOT = QROWS + SEQ * N_KV;
    if (row >= TOT) return;

    float* buf; const float* gamma; const float* beta; int heads; int lrow;
    if (row < QROWS) { buf = qb_; gamma = q_g; beta = q_b; heads = N_HEADS; lrow = row; }
    else             { buf = kb_; gamma = k_g; beta = k_b; heads = N_KV;   lrow = row - QROWS; }

    int s = lrow / heads;
    int lane = threadIdx.x;

    float* p = buf + (size_t)lrow * HEAD_DIM;
    float x0 = p[lane];
    float x1 = p[lane + 32];

    float sum = x0 + x1;
    float sq  = x0 * x0 + x1 * x1;
#pragma unroll
    for (int o = 16; o > 0; o >>= 1) {
        sum += __shfl_xor_sync(0xFFFFFFFFu, sum, o);
        sq  += __shfl_xor_sync(0xFFFFFFFFu, sq,  o);
    }
    float mean = sum * (1.0f / 64.0f);
    float var  = sq * (1.0f / 64.0f) - mean * mean;
    float inv  = rsqrtf(var + 1e-5f);

    float y0 = (x0 - mean) * inv * gamma[lane]      + beta[lane];
    float y1 = (x1 - mean) * inv * gamma[lane + 32] + beta[lane + 32];

    float freq = powf(10000.0f, -(float)lane * (1.0f / 32.0f));
    float ang  = (float)s * freq;
    float c, sn;
    sincosf(ang, &sn, &c);

    p[lane]      = y0 * c - y1 * sn;
    p[lane + 32] = y1 * c + y0 * sn;
}

// ============================================================================
// Tensor-core flash attention (tf32 mma, non-causal, GQA)
// BQ=128, 4 warps x m32. Q, K, P all in FRAGMENT-layout smem:
//   Qf: A-frag per 128x16 chunk (LDS.128)       32 KB
//   Kf: B-frag blocks, stride 66 (LDS.64)        8.25 KB
//   Vs: row-major stride 72 (LDS.32 x2)          9 KB
//   Pf: A-frag per warp/mt (LDS.128)            16 KB
// Q fragments no longer live in registers -> 3 CTAs/SM (launch_bounds).
// ============================================================================
#define AT_BK 32
#define VS_STRIDE 72
#define KF_OFF 8192
#define VS_OFF (KF_OFF + 32 * 66)      // 10304
#define PF_OFF (VS_OFF + 32 * VS_STRIDE)  // 12608
#define ATTN_SMEM_WORDS (PF_OFF + 4096)   // 16704 words = 66816 B

__global__ __launch_bounds__(128, 3) void attn_mma_kernel(
    const float* __restrict__ q, const float* __restrict__ k,
    const float* __restrict__ v, uint32_t* __restrict__ o_frag)
{
    extern __shared__ __align__(16) uint32_t sm[];
    uint32_t* Qf = sm;            // [kt(4)][2048]
    uint32_t* Kf = sm + KF_OFF;   // [(nt*8+ks)(32)][66]
    uint32_t* Vs = sm + VS_OFF;   // [row(32)][72]
    uint32_t* Pf = sm + PF_OFF;   // [(w*2+mt)(8)][512]

    const int h   = blockIdx.y;
    const int g   = h >> 2;
    const int q0  = blockIdx.x * 128;
    const int tid = threadIdx.x;
    const int w   = tid >> 5;      // 0..3
    const int lane = tid & 31;
    const int gid  = lane >> 2;
    const int tig  = lane & 3;

    // ---- stage Q (128x64) into A-fragment layout, once ----
    {
        const float* qb = q + (size_t)q0 * HIDDEN + h * HEAD_DIM;
#pragma unroll
        for (int kt = 0; kt < 4; kt++) {
#pragma unroll
            for (int j = 0; j < 4; j++) {
                int lin = tid + j * 128;
                int arow = lin >> 2, c4 = (lin & 3) * 4;
                float4 vq = *(const float4*)(qb + (size_t)arow * HIDDEN + kt * 16 + c4);
                stage_a(Qf + kt * 2048, vq, lin);
            }
        }
    }

    float o[2][8][4];
#pragma unroll
    for (int mt = 0; mt < 2; mt++)
#pragma unroll
        for (int nt = 0; nt < 8; nt++)
#pragma unroll
            for (int r = 0; r < 4; r++) o[mt][nt][r] = 0.f;
    float m[2][2] = {{-1e30f, -1e30f}, {-1e30f, -1e30f}};
    float l[2][2] = {{0.f, 0.f}, {0.f, 0.f}};

    const float* kbase = k + g * HEAD_DIM;
    const float* vbase = v + g * HEAD_DIM;

    // prefetch tile 0 (4 float4 K + 4 float4 V per thread)
    float4 kf[4], vf[4];
#pragma unroll
    for (int i = 0; i < 4; i++) {
        int f4 = tid + i * 128;
        int row = f4 >> 4, c4 = (f4 & 15) * 4;
        kf[i] = *(const float4*)(kbase + (size_t)row * KV_DIM + c4);
        vf[i] = *(const float4*)(vbase + (size_t)row * KV_DIM + c4);
    }

    const int NT = SEQ / AT_BK;
    for (int t = 0; t < NT; t++) {
        // ---- stage K into fragment layout; V row-major ----
#pragma unroll
        for (int i = 0; i < 4; i++) {
            int f4 = tid + i * 128;
            int row = f4 >> 4, c4 = (f4 & 15) * 4;
            // K frag: block (nt*8+ks), within: (gid_r*4+u)*2 + reg
            int nt_b = row >> 3, gid_r = row & 7;
            int ksb = c4 >> 3, regb = (c4 & 4) >> 2;
            uint32_t* kd = &Kf[(nt_b * 8 + ksb) * 66 + gid_r * 8 + regb];
            kd[0] = f2tf32(kf[i].x); kd[2] = f2tf32(kf[i].y);
            kd[4] = f2tf32(kf[i].z); kd[6] = f2tf32(kf[i].w);
            uint32_t* vd = &Vs[row * VS_STRIDE + c4];
            vd[0] = f2tf32(vf[i].x); vd[1] = f2tf32(vf[i].y);
            vd[2] = f2tf32(vf[i].z); vd[3] = f2tf32(vf[i].w);
        }
        __syncthreads();

        // ---- QK^T: Q a-frags from smem (LDS.128), K b-frags LDS.64 ----
        float s[2][4][4];
#pragma unroll
        for (int mt = 0; mt < 2; mt++)
#pragma unroll
            for (int nt = 0; nt < 4; nt++)
#pragma unroll
                for (int r = 0; r < 4; r++) s[mt][nt][r] = 0.f;
#pragma unroll
        for (int ks = 0; ks < 8; ks++) {
            uint4 a0 = *(const uint4*)&Qf[(ks >> 1) * 2048 +
                        (((w * 2 + 0) * 2 + (ks & 1)) * 32 + lane) * 4];
            uint4 a1 = *(const uint4*)&Qf[(ks >> 1) * 2048 +
                        (((w * 2 + 1) * 2 + (ks & 1)) * 32 + lane) * 4];
            uint32_t ar0[4] = {a0.x, a0.y, a0.z, a0.w};
            uint32_t ar1[4] = {a1.x, a1.y, a1.z, a1.w};
#pragma unroll
            for (int nt = 0; nt < 4; nt++) {
                uint2 bb = *(const uint2*)&Kf[(nt * 8 + ks) * 66 + lane * 2];
                uint32_t br[2] = {bb.x, bb.y};
                mma_tf32(s[0][nt], ar0, br);
                mma_tf32(s[1][nt], ar1, br);
            }
        }

        // prefetch next tile
        if (t + 1 < NT) {
#pragma unroll
            for (int i = 0; i < 4; i++) {
                int f4 = tid + i * 128;
                int row = f4 >> 4, c4 = (f4 & 15) * 4;
                size_t off = (size_t)((t + 1) * AT_BK + row) * KV_DIM + c4;
                kf[i] = *(const float4*)(kbase + off);
                vf[i] = *(const float4*)(vbase + off);
            }
        }

        // ---- online softmax per m-tile; P stored in A-frag layout ----
        const int r2  = 2 * (tig >> 1);
        const int ta0 = (2 * tig) & 3;
        const int ta1 = (2 * tig + 1) & 3;
#pragma unroll
        for (int mt = 0; mt < 2; mt++) {
#pragma unroll
            for (int nt = 0; nt < 4; nt++)
#pragma unroll
                for (int r = 0; r < 4; r++) s[mt][nt][r] *= 0.125f;

            float mr0 = s[mt][0][0], mr1 = s[mt][0][2];
#pragma unroll
            for (int nt = 0; nt < 4; nt++) {
                mr0 = fmaxf(mr0, fmaxf(s[mt][nt][0], s[mt][nt][1]));
                mr1 = fmaxf(mr1, fmaxf(s[mt][nt][2], s[mt][nt][3]));
            }
            mr0 = fmaxf(mr0, __shfl_xor_sync(0xFFFFFFFFu, mr0, 1));
            mr0 = fmaxf(mr0, __shfl_xor_sync(0xFFFFFFFFu, mr0, 2));
            mr1 = fmaxf(mr1, __shfl_xor_sync(0xFFFFFFFFu, mr1, 1));
            mr1 = fmaxf(mr1, __shfl_xor_sync(0xFFFFFFFFu, mr1, 2));

            float mn0 = fmaxf(m[mt][0], mr0), mn1 = fmaxf(m[mt][1], mr1);
            float a0 = __expf(m[mt][0] - mn0), a1 = __expf(m[mt][1] - mn1);
            m[mt][0] = mn0; m[mt][1] = mn1;

            float lp0 = 0.f, lp1 = 0.f;
            uint32_t* Pw = &Pf[(w * 2 + mt) * 512];
#pragma unroll
            for (int nt = 0; nt < 4; nt++) {
                float p00 = __expf(s[mt][nt][0] - mn0);
                float p01 = __expf(s[mt][nt][1] - mn0);
                float p10 = __expf(s[mt][nt][2] - mn1);
                float p11 = __expf(s[mt][nt][3] - mn1);
                lp0 += p00 + p01;
                lp1 += p10 + p11;
                uint32_t* w0 = &Pw[(nt * 32 + gid * 4 + ta0) * 4 + r2];
                uint32_t* w1 = &Pw[(nt * 32 + gid * 4 + ta1) * 4 + r2];
                w0[0] = f2tf32(p00); w0[1] = f2tf32(p10);
                w1[0] = f2tf32(p01); w1[1] = f2tf32(p11);
            }
            lp0 += __shfl_xor_sync(0xFFFFFFFFu, lp0, 1);
            lp0 += __shfl_xor_sync(0xFFFFFFFFu, lp0, 2);
            lp1 += __shfl_xor_sync(0xFFFFFFFFu, lp1, 1);
            lp1 += __shfl_xor_sync(0xFFFFFFFFu, lp1, 2);
            l[mt][0] = l[mt][0] * a0 + lp0;
            l[mt][1] = l[mt][1] * a1 + lp1;

#pragma unroll
            for (int nt = 0; nt < 8; nt++) {
                o[mt][nt][0] *= a0; o[mt][nt][1] *= a0;
                o[mt][nt][2] *= a1; o[mt][nt][3] *= a1;
            }
        }
        __syncwarp();

        // ---- O += P @ V ; P a-frag = 1 LDS.128 per (mt,kj) ----
#pragma unroll
        for (int kj = 0; kj < 4; kj++) {
            uint4 pa0 = *(const uint4*)&Pf[(w * 2 + 0) * 512 + (kj * 32 + lane) * 4];
            uint4 pa1 = *(const uint4*)&Pf[(w * 2 + 1) * 512 + (kj * 32 + lane) * 4];
            uint32_t a0[4] = {pa0.x, pa0.y, pa0.z, pa0.w};
            uint32_t a1[4] = {pa1.x, pa1.y, pa1.z, pa1.w};
#pragma unroll
            for (int nt = 0; nt < 8; nt++) {
                uint32_t b[2];
                const uint32_t* vp = &Vs[(kj * 8 + tig) * VS_STRIDE + nt * 8 + gid];
                b[0] = vp[0];
                b[1] = vp[4 * VS_STRIDE];
                mma_tf32(o[0][nt], a0, b);
                mma_tf32(o[1][nt], a1, b);
            }
        }
        __syncthreads();
    }

    // ---- write O directly into A-fragment layout for the Wo GEMM ----
    const int Kt = HIDDEN / 16;
    const int by = q0 >> 7;
    uint32_t* dstb = o_frag + (size_t)by * Kt * 2048;
    const int cc0 = 2 * tig;
    const int rhi = cc0 >> 2;
    const int t0 = gid * 4 + (cc0 & 3);
    const int t1 = gid * 4 + ((cc0 + 1) & 3);
#pragma unroll
    for (int mt = 0; mt < 2; mt++) {
        const float il0 = 1.0f / l[mt][0], il1 = 1.0f / l[mt][1];
        const int mt_g = w * 2 + mt;
#pragma unroll
        for (int nt = 0; nt < 8; nt++) {
            int kt = h * 4 + (nt >> 1);
            int ks = nt & 1;
            uint32_t* base = dstb + (size_t)kt * 2048 + (size_t)((mt_g * 2 + ks) * 32) * 4;
            base[t0 * 4 + 2 * rhi]     = f2tf32(o[mt][nt][0] * il0);
            base[t1 * 4 + 2 * rhi]     = f2tf32(o[mt][nt][1] * il0);
            base[t0 * 4 + 1 + 2 * rhi] = f2tf32(o[mt][nt][2] * il1);
            base[t1 * 4 + 1 + 2 * rhi] = f2tf32(o[mt][nt][3] * il1);
        }
    }
}

// ---------------- launch --------------------------------------------------
extern "C" void kernel_launch(void* const* d_in, const int* in_sizes, int n_in,
                              void* d_out, int out_size)
{
    const float* x   = (const float*)d_in[0];
    const float* Wq  = (const float*)d_in[1];
    const float* bq  = (const float*)d_in[2];
    const float* Wk  = (const float*)d_in[3];
    const float* bk  = (const float*)d_in[4];
    const float* Wv  = (const float*)d_in[5];
    const float* bv  = (const float*)d_in[6];
    const float* Wo  = (const float*)d_in[7];
    const float* bo  = (const float*)d_in[8];
    const float* q_g = (const float*)d_in[9];
    const float* q_b = (const float*)d_in[10];
    const float* k_g = (const float*)d_in[11];
    const float* k_b = (const float*)d_in[12];
    float* out = (float*)d_out;

    void *pq, *pk, *pv;
    void *pxa, *pwq, *pwk, *pwv, *pwo, *poa;
    cudaGetSymbolAddress(&pq, g_q);
    cudaGetSymbolAddress(&pk, g_k);
    cudaGetSymbolAddress(&pv, g_v);
    cudaGetSymbolAddress(&pxa, g_xa);
    cudaGetSymbolAddress(&pwq, g_wq);
    cudaGetSymbolAddress(&pwk, g_wk);
    cudaGetSymbolAddress(&pwv, g_wv);
    cudaGetSymbolAddress(&pwo, g_wo);
    cudaGetSymbolAddress(&poa, g_oa);
    float* fq = (float*)pq;
    float* fk = (float*)pk;
    float* fv = (float*)pv;
    uint32_t* xa = (uint32_t*)pxa;
    uint32_t* wqf = (uint32_t*)pwq;
    uint32_t* wkf = (uint32_t*)pwk;
    uint32_t* wvf = (uint32_t*)pwv;
    uint32_t* wof = (uint32_t*)pwo;
    uint32_t* oa = (uint32_t*)poa;

    const int GEMM_SMEM = 16 * 2048 * 4;        // 64 KB
    const int ATTN_SMEM = ATTN_SMEM_WORDS * 4;  // ~65.3 KB
    cudaFuncSetAttribute(tf32_gemm_qkv,
                         cudaFuncAttributeMaxDynamicSharedMemorySize, GEMM_SMEM);
    cudaFuncSetAttribute(tf32_gemm_staged,
                         cudaFuncAttributeMaxDynamicSharedMemorySize, GEMM_SMEM);
    cudaFuncSetAttribute(attn_mma_kernel,
                         cudaFuncAttributeMaxDynamicSharedMemorySize, ATTN_SMEM);

    // one combined shuffle launch (x + all 4 weights)
    shuffle_all_kernel<<<3584, 256>>>(x, Wq, Wk, Wv, Wo, xa, wqf, wkf, wvf, wof);

    // fused Q/K/V projections
    {
        dim3 grid(24, SEQ / 128);
        tf32_gemm_qkv<<<grid, 256, GEMM_SMEM>>>(xa, wqf, wkf, wvf,
                                                bq, bk, bv, fq, fk, fv);
    }

    // per-head LN + RoPE (q and k in one launch)
    {
        dim3 blk(32, 4);
        int rows = SEQ * N_HEADS + SEQ * N_KV;
        ln_rope_all<<<(rows + 3) / 4, blk>>>(fq, fk, q_g, q_b, k_g, k_b);
    }

    // attention (BQ=128, 4 warps x m32, fragment-layout smem, 3 CTAs/SM)
    {
        dim3 grid(SEQ / 128, N_HEADS);
        attn_mma_kernel<<<grid, 128, ATTN_SMEM>>>(fq, fk, fv, oa);
    }

    // output projection
    {
        dim3 grid(HIDDEN / 128, SEQ / 128);
        tf32_gemm_staged<<<grid, 256, GEMM_SMEM>>>(oa, wof, bo, out, SEQ, HIDDEN, HIDDEN);
    }
}

// round 10
// speedup vs baseline: 1.0760x; 1.0760x over previous
#include <cuda_runtime.h>
#include <cuda_bf16.h>
#include <math.h>
#include <stdint.h>

// ---------------- problem constants ----------------
#define SEQ      2048
#define HIDDEN   2048
#define N_HEADS  32
#define N_KV     8
#define HEAD_DIM 64
#define KV_DIM   (N_KV * HEAD_DIM)   // 512

// ---------------- scratch ----------------
__device__ float g_q[SEQ * HIDDEN];
__device__ float g_k[SEQ * KV_DIM];
__device__ float g_v[SEQ * KV_DIM];

// fragment-staged operands (tf32 bits). Tile = 2048 words (8KB).
__device__ uint32_t g_xa[(SEQ / 128) * (HIDDEN / 16) * 2048];
__device__ uint32_t g_wq[(HIDDEN / 16) * (HIDDEN / 128) * 2048];
__device__ uint32_t g_wk[(HIDDEN / 16) * (KV_DIM / 128) * 2048];
__device__ uint32_t g_wv[(HIDDEN / 16) * (KV_DIM / 128) * 2048];
__device__ uint32_t g_wo[(HIDDEN / 16) * (HIDDEN / 128) * 2048];
__device__ uint32_t g_oa[(SEQ / 128) * (HIDDEN / 16) * 2048];

__device__ __forceinline__ uint32_t f2tf32(float x) {
    uint32_t r;
    asm("cvt.rna.tf32.f32 %0, %1;" : "=r"(r) : "f"(x));
    return r;
}

__device__ __forceinline__ void mma_tf32(float c[4], const uint32_t a[4], const uint32_t b[2]) {
    asm volatile(
        "mma.sync.aligned.m16n8k8.row.col.f32.tf32.tf32.f32 "
        "{%0,%1,%2,%3},{%4,%5,%6,%7},{%8,%9},{%0,%1,%2,%3};"
        : "+f"(c[0]), "+f"(c[1]), "+f"(c[2]), "+f"(c[3])
        : "r"(a[0]), "r"(a[1]), "r"(a[2]), "r"(a[3]), "r"(b[0]), "r"(b[1]));
}

__device__ __forceinline__ uint32_t smem_u32(const void* p) {
    return (uint32_t)__cvta_generic_to_shared(p);
}
__device__ __forceinline__ void cp_async16(void* smem, const void* gmem) {
    asm volatile("cp.async.cg.shared.global [%0], [%1], 16;"
                 :: "r"(smem_u32(smem)), "l"(gmem));
}
#define CP_COMMIT() asm volatile("cp.async.commit_group;")
#define CP_WAIT2()  asm volatile("cp.async.wait_group 2;")

// ---------------- fragment scatter maps ------------------------------------
__device__ __forceinline__ void stage_a(uint32_t* dst, float4 v, int lin) {
    const int arow = lin >> 2;
    const int cbase = (lin & 3) * 4;
    float vv[4] = {v.x, v.y, v.z, v.w};
#pragma unroll
    for (int u = 0; u < 4; u++) {
        int j  = cbase + u;
        int mt = arow >> 4, rr = arow & 15;
        int ks = j >> 3,    cc = j & 7;
        int t   = (rr & 7) * 4 + (cc & 3);
        int reg = (rr >> 3) + 2 * (cc >> 2);
        dst[((mt * 2 + ks) * 32 + t) * 4 + reg] = f2tf32(vv[u]);
    }
}
__device__ __forceinline__ void stage_b(uint32_t* dst, float4 v, int lin) {
    const int brow = lin >> 5;
    const int cbase = (lin & 31) * 4;
    float vv[4] = {v.x, v.y, v.z, v.w};
#pragma unroll
    for (int u = 0; u < 4; u++) {
        int j  = cbase + u;
        int nt = j >> 3, cc = j & 7;
        int ks = brow >> 3, kk = brow & 7;
        int t   = cc * 4 + (kk & 3);
        int reg = kk >> 2;
        dst[((nt * 2 + ks) * 32 + t) * 2 + reg] = f2tf32(vv[u]);
    }
}

// ---------------- combined shuffle (all operands, one launch) ---------------
__device__ __forceinline__ void shuffle_a_body(
    const float* __restrict__ A, uint32_t* __restrict__ Af,
    int K, int ktp, int by, uint32_t* buf)
{
    const int kt0 = ktp * 2;
    const int Kt = K / 16;
    const int tid = threadIdx.x;
    const int row0 = tid >> 2, c40 = (tid & 3) * 4;
    const int lin1 = 256 + tid;
    const int row1 = lin1 >> 2, c41 = (lin1 & 3) * 4;
    const float* Ab = A + (size_t)(by * 128) * K;

    float4 v[2][2];
#pragma unroll
    for (int t = 0; t < 2; t++) {
        const float* base = Ab + (kt0 + t) * 16;
        v[t][0] = *(const float4*)(base + (size_t)row0 * K + c40);
        v[t][1] = *(const float4*)(base + (size_t)row1 * K + c41);
    }
#pragma unroll
    for (int t = 0; t < 2; t++) {
        stage_a(buf + t * 2048, v[t][0], tid);
        stage_a(buf + t * 2048, v[t][1], lin1);
    }
    __syncthreads();
#pragma unroll
    for (int t = 0; t < 2; t++) {
        uint32_t* dst = Af + ((size_t)by * Kt + kt0 + t) * 2048;
        *(uint4*)(dst + tid * 4)        = *(const uint4*)(buf + t * 2048 + tid * 4);
        *(uint4*)(dst + 1024 + tid * 4) = *(const uint4*)(buf + t * 2048 + 1024 + tid * 4);
    }
}

__device__ __forceinline__ void shuffle_b_body(
    const float* __restrict__ B, uint32_t* __restrict__ Bf,
    int K, int N, int bx, int ktp, uint32_t* buf)
{
    const int kt0 = ktp * 2;
    const int NB = N / 128;
    const int tid = threadIdx.x;
    const int brow0 = tid >> 5, c40 = (tid & 31) * 4;
    const int lin1 = 256 + tid;
    const int brow1 = lin1 >> 5, c41 = (lin1 & 31) * 4;

    float4 v[2][2];
#pragma unroll
    for (int t = 0; t < 2; t++) {
        const float* Bb = B + (size_t)((kt0 + t) * 16) * N + bx * 128;
        v[t][0] = *(const float4*)(Bb + (size_t)brow0 * N + c40);
        v[t][1] = *(const float4*)(Bb + (size_t)brow1 * N + c41);
    }
#pragma unroll
    for (int t = 0; t < 2; t++) {
        stage_b(buf + t * 2048, v[t][0], tid);
        stage_b(buf + t * 2048, v[t][1], lin1);
    }
    __syncthreads();
#pragma unroll
    for (int t = 0; t < 2; t++) {
        uint32_t* dst = Bf + ((size_t)(kt0 + t) * NB + bx) * 2048;
        *(uint4*)(dst + tid * 4)        = *(const uint4*)(buf + t * 2048 + tid * 4);
        *(uint4*)(dst + 1024 + tid * 4) = *(const uint4*)(buf + t * 2048 + 1024 + tid * 4);
    }
}

__global__ __launch_bounds__(256) void shuffle_all_kernel(
    const float* __restrict__ x,
    const float* __restrict__ Wq, const float* __restrict__ Wk,
    const float* __restrict__ Wv, const float* __restrict__ Wo,
    uint32_t* __restrict__ xa, uint32_t* __restrict__ wq,
    uint32_t* __restrict__ wk, uint32_t* __restrict__ wv,
    uint32_t* __restrict__ wo)
{
    __shared__ __align__(16) uint32_t buf[2 * 2048];
    int b = blockIdx.x;
    if (b < 1024) {
        shuffle_a_body(x, xa, HIDDEN, b & 63, b >> 6, buf);
    } else if (b < 2048) {
        b -= 1024;
        shuffle_b_body(Wq, wq, HIDDEN, HIDDEN, b & 15, b >> 4, buf);
    } else if (b < 2304) {
        b -= 2048;
        shuffle_b_body(Wk, wk, HIDDEN, KV_DIM, b & 3, b >> 2, buf);
    } else if (b < 2560) {
        b -= 2304;
        shuffle_b_body(Wv, wv, HIDDEN, KV_DIM, b & 3, b >> 2, buf);
    } else {
        b -= 2560;
        shuffle_b_body(Wo, wo, HIDDEN, HIDDEN, b & 15, b >> 4, buf);
    }
}

// ---------------- GEMM core: 4-stage cp.async, 1 barrier/iter ---------------
__device__ __forceinline__ void gemm_core(
    const uint32_t* __restrict__ Abase,
    const uint32_t* __restrict__ Bf,
    int Kt, int NB, int bxl,
    const float* __restrict__ bias, float* __restrict__ C, int N,
    int by, uint32_t* As, uint32_t* Bs)
{
    const int tid  = threadIdx.x;
    const int lane = tid & 31;
    const int wid  = tid >> 5;
    const int warp_m = wid >> 2;
    const int warp_n = wid & 3;

    float c[4][4][4];
#pragma unroll
    for (int i = 0; i < 4; i++)
#pragma unroll
        for (int j = 0; j < 4; j++)
#pragma unroll
            for (int r = 0; r < 4; r++) c[i][j][r] = 0.f;

    const int o0 = tid * 4;
    const int o1 = 1024 + tid * 4;

#define G_ISSUE(kt_, s_)                                                     \
    do {                                                                     \
        if ((kt_) < Kt) {                                                    \
            const uint32_t* ag = Abase + (size_t)(kt_) * 2048;               \
            const uint32_t* bg = Bf + ((size_t)(kt_) * NB + bxl) * 2048;     \
            cp_async16(&As[(s_) * 2048 + o0], ag + o0);                      \
            cp_async16(&As[(s_) * 2048 + o1], ag + o1);                      \
            cp_async16(&Bs[(s_) * 2048 + o0], bg + o0);                      \
            cp_async16(&Bs[(s_) * 2048 + o1], bg + o1);                      \
        }                                                                    \
        CP_COMMIT();                                                         \
    } while (0)

    G_ISSUE(0, 0);
    G_ISSUE(1, 1);
    G_ISSUE(2, 2);

    for (int kt = 0; kt < Kt; kt++) {
        const int s = kt & 3;
        CP_WAIT2();
        __syncthreads();
        G_ISSUE(kt + 3, (kt + 3) & 3);

        const uint32_t* Ass = &As[s * 2048];
        const uint32_t* Bss = &Bs[s * 2048];
#pragma unroll
        for (int ks = 0; ks < 2; ks++) {
            uint4 a[4];
            uint2 b[4];
#pragma unroll
            for (int mt = 0; mt < 4; mt++)
                a[mt] = *(const uint4*)&Ass[(((warp_m * 4 + mt) * 2 + ks) * 32 + lane) * 4];
#pragma unroll
            for (int nt = 0; nt < 4; nt++)
                b[nt] = *(const uint2*)&Bss[(((warp_n * 4 + nt) * 2 + ks) * 32 + lane) * 2];
#pragma unroll
            for (int mt = 0; mt < 4; mt++)
#pragma unroll
                for (int nt = 0; nt < 4; nt++) {
                    uint32_t ar[4] = {a[mt].x, a[mt].y, a[mt].z, a[mt].w};
                    uint32_t br[2] = {b[nt].x, b[nt].y};
                    mma_tf32(c[mt][nt], ar, br);
                }
        }
    }
#undef G_ISSUE

#pragma unroll
    for (int mt = 0; mt < 4; mt++) {
        int gr = by * 128 + warp_m * 64 + mt * 16 + (lane >> 2);
#pragma unroll
        for (int nt = 0; nt < 4; nt++) {
            int gc = bxl * 128 + warp_n * 32 + nt * 8 + (lane & 3) * 2;
            float b0 = bias[gc], b1 = bias[gc + 1];
            float2 r0 = {c[mt][nt][0] + b0, c[mt][nt][1] + b1};
            float2 r1 = {c[mt][nt][2] + b0, c[mt][nt][3] + b1};
            *(float2*)(C + (size_t)gr * N + gc) = r0;
            *(float2*)(C + (size_t)(gr + 8) * N + gc) = r1;
        }
    }
}

__global__ __launch_bounds__(256) void tf32_gemm_qkv(
    const uint32_t* __restrict__ Af,
    const uint32_t* __restrict__ Bq, const uint32_t* __restrict__ Bk,
    const uint32_t* __restrict__ Bv,
    const float* __restrict__ bq, const float* __restrict__ bk,
    const float* __restrict__ bv,
    float* __restrict__ cq, float* __restrict__ ck, float* __restrict__ cv)
{
    extern __shared__ __align__(16) uint32_t smem[];
    uint32_t* As = smem;
    uint32_t* Bs = smem + 4 * 2048;

    const int bx = blockIdx.x;
    const int by = blockIdx.y;
    const int Kt = HIDDEN / 16;

    const uint32_t* Bf;
    const float* bias;
    float* C;
    int N, NB, bxl;
    if (bx < 16)      { Bf = Bq; bias = bq; C = cq; N = HIDDEN; NB = 16; bxl = bx; }
    else if (bx < 20) { Bf = Bk; bias = bk; C = ck; N = KV_DIM; NB = 4;  bxl = bx - 16; }
    else              { Bf = Bv; bias = bv; C = cv; N = KV_DIM; NB = 4;  bxl = bx - 20; }

    gemm_core(Af + (size_t)by * Kt * 2048, Bf, Kt, NB, bxl, bias, C, N, by, As, Bs);
}

__global__ __launch_bounds__(256) void tf32_gemm_staged(
    const uint32_t* __restrict__ Af, const uint32_t* __restrict__ Bf,
    const float* __restrict__ bias, float* __restrict__ C,
    int M, int N, int K)
{
    extern __shared__ __align__(16) uint32_t smem[];
    uint32_t* As = smem;
    uint32_t* Bs = smem + 4 * 2048;
    const int Kt = K / 16;
    gemm_core(Af + (size_t)blockIdx.y * Kt * 2048, Bf, Kt, N / 128, blockIdx.x,
              bias, C, N, blockIdx.y, As, Bs);
}

// ---------------- fused per-head LayerNorm + RoPE (q and k, one launch) -----
__global__ void ln_rope_all(float* __restrict__ qb_, float* __restrict__ kb_,
                            const float* __restrict__ q_g, const float* __restrict__ q_b,
                            const float* __restrict__ k_g, const float* __restrict__ k_b)
{
    int row = blockIdx.x * blockDim.y + threadIdx.y;
    const int QROWS = SEQ * N_HEADS;
    const int TOT = QROWS + SEQ * N_KV;
    if (row >= TOT) return;

    float* buf; const float* gamma; const float* beta; int heads; int lrow;
    if (row < QROWS) { buf = qb_; gamma = q_g; beta = q_b; heads = N_HEADS; lrow = row; }
    else             { buf = kb_; gamma = k_g; beta = k_b; heads = N_KV;   lrow = row - QROWS; }

    int s = lrow / heads;
    int lane = threadIdx.x;

    float* p = buf + (size_t)lrow * HEAD_DIM;
    float x0 = p[lane];
    float x1 = p[lane + 32];

    float sum = x0 + x1;
    float sq  = x0 * x0 + x1 * x1;
#pragma unroll
    for (int o = 16; o > 0; o >>= 1) {
        sum += __shfl_xor_sync(0xFFFFFFFFu, sum, o);
        sq  += __shfl_xor_sync(0xFFFFFFFFu, sq,  o);
    }
    float mean = sum * (1.0f / 64.0f);
    float var  = sq * (1.0f / 64.0f) - mean * mean;
    float inv  = rsqrtf(var + 1e-5f);

    float y0 = (x0 - mean) * inv * gamma[lane]      + beta[lane];
    float y1 = (x1 - mean) * inv * gamma[lane + 32] + beta[lane + 32];

    float freq = powf(10000.0f, -(float)lane * (1.0f / 32.0f));
    float ang  = (float)s * freq;
    float c, sn;
    sincosf(ang, &sn, &c);

    p[lane]      = y0 * c - y1 * sn;
    p[lane + 32] = y1 * c + y0 * sn;
}

// ============================================================================
// Tensor-core flash attention (tf32 mma, non-causal, GQA)
// R8 base (Q fragments in REGISTERS, BQ=128, 4 warps x m32) with reduced
// LSU issue count:
//   Kf: b-frag blocks, stride 66  -> 1 LDS.64 per (ks,nt)
//   Vf: b-frag blocks, stride 66  -> 1 LDS.64 per (kj,nt)
//   Pf: A-frag layout             -> 1 LDS.128 per (mt,kj)
// ============================================================================
#define AT_BK 32

__global__ __launch_bounds__(128) void attn_mma_kernel(
    const float* __restrict__ q, const float* __restrict__ k,
    const float* __restrict__ v, uint32_t* __restrict__ o_frag)
{
    __shared__ uint32_t Kf[32 * 66];                 // [(nt*8+ks)][66]
    __shared__ uint32_t Vf[32 * 66];                 // [(nt*4+kj)][66]
    __shared__ __align__(16) uint32_t Pf[8 * 512];   // [(w*2+mt)][512] A-frag

    const int h   = blockIdx.y;
    const int g   = h >> 2;
    const int q0  = blockIdx.x * 128;
    const int tid = threadIdx.x;
    const int w   = tid >> 5;      // 0..3
    const int lane = tid & 31;
    const int gid  = lane >> 2;
    const int tig  = lane & 3;

    // ---- Q fragments in registers (R8) ----
    uint32_t qf[2][8][4];
#pragma unroll
    for (int mt = 0; mt < 2; mt++) {
        const float* qp = q + (size_t)(q0 + w * 32 + mt * 16) * HIDDEN + h * HEAD_DIM;
#pragma unroll
        for (int ks = 0; ks < 8; ks++) {
            qf[mt][ks][0] = f2tf32(qp[(size_t)gid       * HIDDEN + ks * 8 + tig]);
            qf[mt][ks][1] = f2tf32(qp[(size_t)(gid + 8) * HIDDEN + ks * 8 + tig]);
            qf[mt][ks][2] = f2tf32(qp[(size_t)gid       * HIDDEN + ks * 8 + tig + 4]);
            qf[mt][ks][3] = f2tf32(qp[(size_t)(gid + 8) * HIDDEN + ks * 8 + tig + 4]);
        }
    }

    float o[2][8][4];
#pragma unroll
    for (int mt = 0; mt < 2; mt++)
#pragma unroll
        for (int nt = 0; nt < 8; nt++)
#pragma unroll
            for (int r = 0; r < 4; r++) o[mt][nt][r] = 0.f;
    float m[2][2] = {{-1e30f, -1e30f}, {-1e30f, -1e30f}};
    float l[2][2] = {{0.f, 0.f}, {0.f, 0.f}};

    const float* kbase = k + g * HEAD_DIM;
    const float* vbase = v + g * HEAD_DIM;

    // prefetch tile 0 (4 float4 K + 4 float4 V per thread)
    float4 kf[4], vf[4];
#pragma unroll
    for (int i = 0; i < 4; i++) {
        int f4 = tid + i * 128;
        int row = f4 >> 4, c4 = (f4 & 15) * 4;
        kf[i] = *(const float4*)(kbase + (size_t)row * KV_DIM + c4);
        vf[i] = *(const float4*)(vbase + (size_t)row * KV_DIM + c4);
    }

    const int NT = SEQ / AT_BK;
    for (int t = 0; t < NT; t++) {
        // ---- stage K and V into b-fragment layouts ----
#pragma unroll
        for (int i = 0; i < 4; i++) {
            int f4 = tid + i * 128;
            int row = f4 >> 4, c4 = (f4 & 15) * 4;
            // K: element K[row][c] -> block (nt*8+ks), word gid*8 + tig*2 + reg
            //    row = kv row = n-dim: ntb=row>>3, gidb=row&7
            //    c = head dim = k-dim: ks=c>>3, tigb=c&3, regb=(c&4)>>2
            {
                int ntb = row >> 3, gidb = row & 7;
                int ksb = c4 >> 3, regb = (c4 & 4) >> 2;
                uint32_t* kd = &Kf[(ntb * 8 + ksb) * 66 + gidb * 8 + regb];
                kd[0] = f2tf32(kf[i].x); kd[2] = f2tf32(kf[i].y);
                kd[4] = f2tf32(kf[i].z); kd[6] = f2tf32(kf[i].w);
            }
            // V: element V[row][c] -> block (nt*4+kj), word gid*8 + tig*2 + reg
            //    row = kv row = k-dim: kj=row>>3, tigv=(row&7)&3, regv=(row&7)>>2
            //    c = out dim = n-dim: nt=c>>3, gidv=c&7
            {
                int kj = row >> 3, r8 = row & 7;
                int tigv = r8 & 3, regv = r8 >> 2;
                float vals[4] = {vf[i].x, vf[i].y, vf[i].z, vf[i].w};
#pragma unroll
                for (int u = 0; u < 4; u++) {
                    int c = c4 + u;
                    int ntv = c >> 3, gidv = c & 7;
                    Vf[(ntv * 4 + kj) * 66 + gidv * 8 + tigv * 2 + regv] = f2tf32(vals[u]);
                }
            }
        }
        __syncthreads();

        // ---- QK^T: K b-frag = one LDS.64 per (ks,nt) ----
        float s[2][4][4];
#pragma unroll
        for (int mt = 0; mt < 2; mt++)
#pragma unroll
            for (int nt = 0; nt < 4; nt++)
#pragma unroll
                for (int r = 0; r < 4; r++) s[mt][nt][r] = 0.f;
#pragma unroll
        for (int ks = 0; ks < 8; ks++) {
#pragma unroll
            for (int nt = 0; nt < 4; nt++) {
                uint2 bb = *(const uint2*)&Kf[(nt * 8 + ks) * 66 + lane * 2];
                uint32_t br[2] = {bb.x, bb.y};
                mma_tf32(s[0][nt], qf[0][ks], br);
                mma_tf32(s[1][nt], qf[1][ks], br);
            }
        }

        // prefetch next tile
        if (t + 1 < NT) {
#pragma unroll
            for (int i = 0; i < 4; i++) {
                int f4 = tid + i * 128;
                int row = f4 >> 4, c4 = (f4 & 15) * 4;
                size_t off = (size_t)((t + 1) * AT_BK + row) * KV_DIM + c4;
                kf[i] = *(const float4*)(kbase + off);
                vf[i] = *(const float4*)(vbase + off);
            }
        }

        // ---- online softmax per m-tile; P stored in A-frag layout ----
        const int r2  = 2 * (tig >> 1);
        const int ta0 = (2 * tig) & 3;
        const int ta1 = (2 * tig + 1) & 3;
#pragma unroll
        for (int mt = 0; mt < 2; mt++) {
#pragma unroll
            for (int nt = 0; nt < 4; nt++)
#pragma unroll
                for (int r = 0; r < 4; r++) s[mt][nt][r] *= 0.125f;

            float mr0 = s[mt][0][0], mr1 = s[mt][0][2];
#pragma unroll
            for (int nt = 0; nt < 4; nt++) {
                mr0 = fmaxf(mr0, fmaxf(s[mt][nt][0], s[mt][nt][1]));
                mr1 = fmaxf(mr1, fmaxf(s[mt][nt][2], s[mt][nt][3]));
            }
            mr0 = fmaxf(mr0, __shfl_xor_sync(0xFFFFFFFFu, mr0, 1));
            mr0 = fmaxf(mr0, __shfl_xor_sync(0xFFFFFFFFu, mr0, 2));
            mr1 = fmaxf(mr1, __shfl_xor_sync(0xFFFFFFFFu, mr1, 1));
            mr1 = fmaxf(mr1, __shfl_xor_sync(0xFFFFFFFFu, mr1, 2));

            float mn0 = fmaxf(m[mt][0], mr0), mn1 = fmaxf(m[mt][1], mr1);
            float a0 = __expf(m[mt][0] - mn0), a1 = __expf(m[mt][1] - mn1);
            m[mt][0] = mn0; m[mt][1] = mn1;

            float lp0 = 0.f, lp1 = 0.f;
            uint32_t* Pw = &Pf[(w * 2 + mt) * 512];
#pragma unroll
            for (int nt = 0; nt < 4; nt++) {
                float p00 = __expf(s[mt][nt][0] - mn0);
                float p01 = __expf(s[mt][nt][1] - mn0);
                float p10 = __expf(s[mt][nt][2] - mn1);
                float p11 = __expf(s[mt][nt][3] - mn1);
                lp0 += p00 + p01;
                lp1 += p10 + p11;
                uint32_t* w0 = &Pw[(nt * 32 + gid * 4 + ta0) * 4 + r2];
                uint32_t* w1 = &Pw[(nt * 32 + gid * 4 + ta1) * 4 + r2];
                w0[0] = f2tf32(p00); w0[1] = f2tf32(p10);
                w1[0] = f2tf32(p01); w1[1] = f2tf32(p11);
            }
            lp0 += __shfl_xor_sync(0xFFFFFFFFu, lp0, 1);
            lp0 += __shfl_xor_sync(0xFFFFFFFFu, lp0, 2);
            lp1 += __shfl_xor_sync(0xFFFFFFFFu, lp1, 1);
            lp1 += __shfl_xor_sync(0xFFFFFFFFu, lp1, 2);
            l[mt][0] = l[mt][0] * a0 + lp0;
            l[mt][1] = l[mt][1] * a1 + lp1;

#pragma unroll
            for (int nt = 0; nt < 8; nt++) {
                o[mt][nt][0] *= a0; o[mt][nt][1] *= a0;
                o[mt][nt][2] *= a1; o[mt][nt][3] *= a1;
            }
        }
        __syncwarp();

        // ---- O += P @ V ; P a-frag LDS.128, V b-frag LDS.64 ----
#pragma unroll
        for (int kj = 0; kj < 4; kj++) {
            uint4 pa0 = *(const uint4*)&Pf[(w * 2 + 0) * 512 + (kj * 32 + lane) * 4];
            uint4 pa1 = *(const uint4*)&Pf[(w * 2 + 1) * 512 + (kj * 32 + lane) * 4];
            uint32_t a0[4] = {pa0.x, pa0.y, pa0.z, pa0.w};
            uint32_t a1[4] = {pa1.x, pa1.y, pa1.z, pa1.w};
#pragma unroll
            for (int nt = 0; nt < 8; nt++) {
                uint2 bb = *(const uint2*)&Vf[(nt * 4 + kj) * 66 + lane * 2];
                uint32_t br[2] = {bb.x, bb.y};
                mma_tf32(o[0][nt], a0, br);
                mma_tf32(o[1][nt], a1, br);
            }
        }
        __syncthreads();
    }

    // ---- write O directly into A-fragment layout for the Wo GEMM ----
    const int Kt = HIDDEN / 16;
    const int by = q0 >> 7;
    uint32_t* dstb = o_frag + (size_t)by * Kt * 2048;
    const int cc0 = 2 * tig;
    const int rhi = cc0 >> 2;
    const int t0 = gid * 4 + (cc0 & 3);
    const int t1 = gid * 4 + ((cc0 + 1) & 3);
#pragma unroll
    for (int mt = 0; mt < 2; mt++) {
        const float il0 = 1.0f / l[mt][0], il1 = 1.0f / l[mt][1];
        const int mt_g = w * 2 + mt;
#pragma unroll
        for (int nt = 0; nt < 8; nt++) {
            int kt = h * 4 + (nt >> 1);
            int ks = nt & 1;
            uint32_t* base = dstb + (size_t)kt * 2048 + (size_t)((mt_g * 2 + ks) * 32) * 4;
            base[t0 * 4 + 2 * rhi]     = f2tf32(o[mt][nt][0] * il0);
            base[t1 * 4 + 2 * rhi]     = f2tf32(o[mt][nt][1] * il0);
            base[t0 * 4 + 1 + 2 * rhi] = f2tf32(o[mt][nt][2] * il1);
            base[t1 * 4 + 1 + 2 * rhi] = f2tf32(o[mt][nt][3] * il1);
        }
    }
}

// ---------------- launch --------------------------------------------------
extern "C" void kernel_launch(void* const* d_in, const int* in_sizes, int n_in,
                              void* d_out, int out_size)
{
    const float* x   = (const float*)d_in[0];
    const float* Wq  = (const float*)d_in[1];
    const float* bq  = (const float*)d_in[2];
    const float* Wk  = (const float*)d_in[3];
    const float* bk  = (const float*)d_in[4];
    const float* Wv  = (const float*)d_in[5];
    const float* bv  = (const float*)d_in[6];
    const float* Wo  = (const float*)d_in[7];
    const float* bo  = (const float*)d_in[8];
    const float* q_g = (const float*)d_in[9];
    const float* q_b = (const float*)d_in[10];
    const float* k_g = (const float*)d_in[11];
    const float* k_b = (const float*)d_in[12];
    float* out = (float*)d_out;

    void *pq, *pk, *pv;
    void *pxa, *pwq, *pwk, *pwv, *pwo, *poa;
    cudaGetSymbolAddress(&pq, g_q);
    cudaGetSymbolAddress(&pk, g_k);
    cudaGetSymbolAddress(&pv, g_v);
    cudaGetSymbolAddress(&pxa, g_xa);
    cudaGetSymbolAddress(&pwq, g_wq);
    cudaGetSymbolAddress(&pwk, g_wk);
    cudaGetSymbolAddress(&pwv, g_wv);
    cudaGetSymbolAddress(&pwo, g_wo);
    cudaGetSymbolAddress(&poa, g_oa);
    float* fq = (float*)pq;
    float* fk = (float*)pk;
    float* fv = (float*)pv;
    uint32_t* xa = (uint32_t*)pxa;
    uint32_t* wqf = (uint32_t*)pwq;
    uint32_t* wkf = (uint32_t*)pwk;
    uint32_t* wvf = (uint32_t*)pwv;
    uint32_t* wof = (uint32_t*)pwo;
    uint32_t* oa = (uint32_t*)poa;

    const int GEMM_SMEM = 16 * 2048 * 4;   // 64 KB
    cudaFuncSetAttribute(tf32_gemm_qkv,
                         cudaFuncAttributeMaxDynamicSharedMemorySize, GEMM_SMEM);
    cudaFuncSetAttribute(tf32_gemm_staged,
                         cudaFuncAttributeMaxDynamicSharedMemorySize, GEMM_SMEM);

    // one combined shuffle launch (x + all 4 weights)
    shuffle_all_kernel<<<3584, 256>>>(x, Wq, Wk, Wv, Wo, xa, wqf, wkf, wvf, wof);

    // fused Q/K/V projections
    {
        dim3 grid(24, SEQ / 128);
        tf32_gemm_qkv<<<grid, 256, GEMM_SMEM>>>(xa, wqf, wkf, wvf,
                                                bq, bk, bv, fq, fk, fv);
    }

    // per-head LN + RoPE (q and k in one launch)
    {
        dim3 blk(32, 4);
        int rows = SEQ * N_HEADS + SEQ * N_KV;
        ln_rope_all<<<(rows + 3) / 4, blk>>>(fq, fk, q_g, q_b, k_g, k_b);
    }

    // attention (BQ=128, 4 warps x m32, vectorized fragment smem)
    {
        dim3 grid(SEQ / 128, N_HEADS);
        attn_mma_kernel<<<grid, 128>>>(fq, fk, fv, oa);
    }

    // output projection
    {
        dim3 grid(HIDDEN / 128, SEQ / 128);
        tf32_gemm_staged<<<grid, 256, GEMM_SMEM>>>(oa, wof, bo, out, SEQ, HIDDEN, HIDDEN);
    }
}

// round 11
// speedup vs baseline: 1.0871x; 1.0103x over previous
#include <cuda_runtime.h>
#include <cuda_bf16.h>
#include <math.h>
#include <stdint.h>

// ---------------- problem constants ----------------
#define SEQ      2048
#define HIDDEN   2048
#define N_HEADS  32
#define N_KV     8
#define HEAD_DIM 64
#define KV_DIM   (N_KV * HEAD_DIM)   // 512

// ---------------- scratch ----------------
__device__ float g_q[SEQ * HIDDEN];
__device__ float g_k[SEQ * KV_DIM];
__device__ float g_v[SEQ * KV_DIM];

// fragment-staged GEMM operands (tf32 bits). Tile = 2048 words (8KB).
__device__ uint32_t g_xa[(SEQ / 128) * (HIDDEN / 16) * 2048];
__device__ uint32_t g_wq[(HIDDEN / 16) * (HIDDEN / 128) * 2048];
__device__ uint32_t g_wk[(HIDDEN / 16) * (KV_DIM / 128) * 2048];
__device__ uint32_t g_wv[(HIDDEN / 16) * (KV_DIM / 128) * 2048];
__device__ uint32_t g_wo[(HIDDEN / 16) * (HIDDEN / 128) * 2048];
__device__ uint32_t g_oa[(SEQ / 128) * (HIDDEN / 16) * 2048];

// fragment-staged K/V for attention: [g(8)][tile(64)][2048 words]
__device__ uint32_t g_kf[N_KV * (SEQ / 32) * 2048];   // 4 MB
__device__ uint32_t g_vf[N_KV * (SEQ / 32) * 2048];   // 4 MB

__device__ __forceinline__ uint32_t f2tf32(float x) {
    uint32_t r;
    asm("cvt.rna.tf32.f32 %0, %1;" : "=r"(r) : "f"(x));
    return r;
}

__device__ __forceinline__ void mma_tf32(float c[4], const uint32_t a[4], const uint32_t b[2]) {
    asm volatile(
        "mma.sync.aligned.m16n8k8.row.col.f32.tf32.tf32.f32 "
        "{%0,%1,%2,%3},{%4,%5,%6,%7},{%8,%9},{%0,%1,%2,%3};"
        : "+f"(c[0]), "+f"(c[1]), "+f"(c[2]), "+f"(c[3])
        : "r"(a[0]), "r"(a[1]), "r"(a[2]), "r"(a[3]), "r"(b[0]), "r"(b[1]));
}

__device__ __forceinline__ uint32_t smem_u32(const void* p) {
    return (uint32_t)__cvta_generic_to_shared(p);
}
__device__ __forceinline__ void cp_async16(void* smem, const void* gmem) {
    asm volatile("cp.async.cg.shared.global [%0], [%1], 16;"
                 :: "r"(smem_u32(smem)), "l"(gmem));
}
#define CP_COMMIT() asm volatile("cp.async.commit_group;")
#define CP_WAIT2()  asm volatile("cp.async.wait_group 2;")

// ---------------- fragment scatter maps ------------------------------------
__device__ __forceinline__ void stage_a(uint32_t* dst, float4 v, int lin) {
    const int arow = lin >> 2;
    const int cbase = (lin & 3) * 4;
    float vv[4] = {v.x, v.y, v.z, v.w};
#pragma unroll
    for (int u = 0; u < 4; u++) {
        int j  = cbase + u;
        int mt = arow >> 4, rr = arow & 15;
        int ks = j >> 3,    cc = j & 7;
        int t   = (rr & 7) * 4 + (cc & 3);
        int reg = (rr >> 3) + 2 * (cc >> 2);
        dst[((mt * 2 + ks) * 32 + t) * 4 + reg] = f2tf32(vv[u]);
    }
}
__device__ __forceinline__ void stage_b(uint32_t* dst, float4 v, int lin) {
    const int brow = lin >> 5;
    const int cbase = (lin & 31) * 4;
    float vv[4] = {v.x, v.y, v.z, v.w};
#pragma unroll
    for (int u = 0; u < 4; u++) {
        int j  = cbase + u;
        int nt = j >> 3, cc = j & 7;
        int ks = brow >> 3, kk = brow & 7;
        int t   = cc * 4 + (kk & 3);
        int reg = kk >> 2;
        dst[((nt * 2 + ks) * 32 + t) * 2 + reg] = f2tf32(vv[u]);
    }
}

// ---------------- combined shuffle (all operands, one launch) ---------------
__device__ __forceinline__ void shuffle_a_body(
    const float* __restrict__ A, uint32_t* __restrict__ Af,
    int K, int ktp, int by, uint32_t* buf)
{
    const int kt0 = ktp * 2;
    const int Kt = K / 16;
    const int tid = threadIdx.x;
    const int row0 = tid >> 2, c40 = (tid & 3) * 4;
    const int lin1 = 256 + tid;
    const int row1 = lin1 >> 2, c41 = (lin1 & 3) * 4;
    const float* Ab = A + (size_t)(by * 128) * K;

    float4 v[2][2];
#pragma unroll
    for (int t = 0; t < 2; t++) {
        const float* base = Ab + (kt0 + t) * 16;
        v[t][0] = *(const float4*)(base + (size_t)row0 * K + c40);
        v[t][1] = *(const float4*)(base + (size_t)row1 * K + c41);
    }
#pragma unroll
    for (int t = 0; t < 2; t++) {
        stage_a(buf + t * 2048, v[t][0], tid);
        stage_a(buf + t * 2048, v[t][1], lin1);
    }
    __syncthreads();
#pragma unroll
    for (int t = 0; t < 2; t++) {
        uint32_t* dst = Af + ((size_t)by * Kt + kt0 + t) * 2048;
        *(uint4*)(dst + tid * 4)        = *(const uint4*)(buf + t * 2048 + tid * 4);
        *(uint4*)(dst + 1024 + tid * 4) = *(const uint4*)(buf + t * 2048 + 1024 + tid * 4);
    }
}

__device__ __forceinline__ void shuffle_b_body(
    const float* __restrict__ B, uint32_t* __restrict__ Bf,
    int K, int N, int bx, int ktp, uint32_t* buf)
{
    const int kt0 = ktp * 2;
    const int NB = N / 128;
    const int tid = threadIdx.x;
    const int brow0 = tid >> 5, c40 = (tid & 31) * 4;
    const int lin1 = 256 + tid;
    const int brow1 = lin1 >> 5, c41 = (lin1 & 31) * 4;

    float4 v[2][2];
#pragma unroll
    for (int t = 0; t < 2; t++) {
        const float* Bb = B + (size_t)((kt0 + t) * 16) * N + bx * 128;
        v[t][0] = *(const float4*)(Bb + (size_t)brow0 * N + c40);
        v[t][1] = *(const float4*)(Bb + (size_t)brow1 * N + c41);
    }
#pragma unroll
    for (int t = 0; t < 2; t++) {
        stage_b(buf + t * 2048, v[t][0], tid);
        stage_b(buf + t * 2048, v[t][1], lin1);
    }
    __syncthreads();
#pragma unroll
    for (int t = 0; t < 2; t++) {
        uint32_t* dst = Bf + ((size_t)(kt0 + t) * NB + bx) * 2048;
        *(uint4*)(dst + tid * 4)        = *(const uint4*)(buf + t * 2048 + tid * 4);
        *(uint4*)(dst + 1024 + tid * 4) = *(const uint4*)(buf + t * 2048 + 1024 + tid * 4);
    }
}

__global__ __launch_bounds__(256) void shuffle_all_kernel(
    const float* __restrict__ x,
    const float* __restrict__ Wq, const float* __restrict__ Wk,
    const float* __restrict__ Wv, const float* __restrict__ Wo,
    uint32_t* __restrict__ xa, uint32_t* __restrict__ wq,
    uint32_t* __restrict__ wk, uint32_t* __restrict__ wv,
    uint32_t* __restrict__ wo)
{
    __shared__ __align__(16) uint32_t buf[2 * 2048];
    int b = blockIdx.x;
    if (b < 1024) {
        shuffle_a_body(x, xa, HIDDEN, b & 63, b >> 6, buf);
    } else if (b < 2048) {
        b -= 1024;
        shuffle_b_body(Wq, wq, HIDDEN, HIDDEN, b & 15, b >> 4, buf);
    } else if (b < 2304) {
        b -= 2048;
        shuffle_b_body(Wk, wk, HIDDEN, KV_DIM, b & 3, b >> 2, buf);
    } else if (b < 2560) {
        b -= 2304;
        shuffle_b_body(Wv, wv, HIDDEN, KV_DIM, b & 3, b >> 2, buf);
    } else {
        b -= 2560;
        shuffle_b_body(Wo, wo, HIDDEN, HIDDEN, b & 15, b >> 4, buf);
    }
}

// ---------------- GEMM core: 4-stage cp.async, 1 barrier/iter ---------------
__device__ __forceinline__ void gemm_core(
    const uint32_t* __restrict__ Abase,
    const uint32_t* __restrict__ Bf,
    int Kt, int NB, int bxl,
    const float* __restrict__ bias, float* __restrict__ C, int N,
    int by, uint32_t* As, uint32_t* Bs)
{
    const int tid  = threadIdx.x;
    const int lane = tid & 31;
    const int wid  = tid >> 5;
    const int warp_m = wid >> 2;
    const int warp_n = wid & 3;

    float c[4][4][4];
#pragma unroll
    for (int i = 0; i < 4; i++)
#pragma unroll
        for (int j = 0; j < 4; j++)
#pragma unroll
            for (int r = 0; r < 4; r++) c[i][j][r] = 0.f;

    const int o0 = tid * 4;
    const int o1 = 1024 + tid * 4;

#define G_ISSUE(kt_, s_)                                                     \
    do {                                                                     \
        if ((kt_) < Kt) {                                                    \
            const uint32_t* ag = Abase + (size_t)(kt_) * 2048;               \
            const uint32_t* bg = Bf + ((size_t)(kt_) * NB + bxl) * 2048;     \
            cp_async16(&As[(s_) * 2048 + o0], ag + o0);                      \
            cp_async16(&As[(s_) * 2048 + o1], ag + o1);                      \
            cp_async16(&Bs[(s_) * 2048 + o0], bg + o0);                      \
            cp_async16(&Bs[(s_) * 2048 + o1], bg + o1);                      \
        }                                                                    \
        CP_COMMIT();                                                         \
    } while (0)

    G_ISSUE(0, 0);
    G_ISSUE(1, 1);
    G_ISSUE(2, 2);

    for (int kt = 0; kt < Kt; kt++) {
        const int s = kt & 3;
        CP_WAIT2();
        __syncthreads();
        G_ISSUE(kt + 3, (kt + 3) & 3);

        const uint32_t* Ass = &As[s * 2048];
        const uint32_t* Bss = &Bs[s * 2048];
#pragma unroll
        for (int ks = 0; ks < 2; ks++) {
            uint4 a[4];
            uint2 b[4];
#pragma unroll
            for (int mt = 0; mt < 4; mt++)
                a[mt] = *(const uint4*)&Ass[(((warp_m * 4 + mt) * 2 + ks) * 32 + lane) * 4];
#pragma unroll
            for (int nt = 0; nt < 4; nt++)
                b[nt] = *(const uint2*)&Bss[(((warp_n * 4 + nt) * 2 + ks) * 32 + lane) * 2];
#pragma unroll
            for (int mt = 0; mt < 4; mt++)
#pragma unroll
                for (int nt = 0; nt < 4; nt++) {
                    uint32_t ar[4] = {a[mt].x, a[mt].y, a[mt].z, a[mt].w};
                    uint32_t br[2] = {b[nt].x, b[nt].y};
                    mma_tf32(c[mt][nt], ar, br);
                }
        }
    }
#undef G_ISSUE

#pragma unroll
    for (int mt = 0; mt < 4; mt++) {
        int gr = by * 128 + warp_m * 64 + mt * 16 + (lane >> 2);
#pragma unroll
        for (int nt = 0; nt < 4; nt++) {
            int gc = bxl * 128 + warp_n * 32 + nt * 8 + (lane & 3) * 2;
            float b0 = bias[gc], b1 = bias[gc + 1];
            float2 r0 = {c[mt][nt][0] + b0, c[mt][nt][1] + b1};
            float2 r1 = {c[mt][nt][2] + b0, c[mt][nt][3] + b1};
            *(float2*)(C + (size_t)gr * N + gc) = r0;
            *(float2*)(C + (size_t)(gr + 8) * N + gc) = r1;
        }
    }
}

__global__ __launch_bounds__(256) void tf32_gemm_qkv(
    const uint32_t* __restrict__ Af,
    const uint32_t* __restrict__ Bq, const uint32_t* __restrict__ Bk,
    const uint32_t* __restrict__ Bv,
    const float* __restrict__ bq, const float* __restrict__ bk,
    const float* __restrict__ bv,
    float* __restrict__ cq, float* __restrict__ ck, float* __restrict__ cv)
{
    extern __shared__ __align__(16) uint32_t smem[];
    uint32_t* As = smem;
    uint32_t* Bs = smem + 4 * 2048;

    const int bx = blockIdx.x;
    const int by = blockIdx.y;
    const int Kt = HIDDEN / 16;

    const uint32_t* Bf;
    const float* bias;
    float* C;
    int N, NB, bxl;
    if (bx < 16)      { Bf = Bq; bias = bq; C = cq; N = HIDDEN; NB = 16; bxl = bx; }
    else if (bx < 20) { Bf = Bk; bias = bk; C = ck; N = KV_DIM; NB = 4;  bxl = bx - 16; }
    else              { Bf = Bv; bias = bv; C = cv; N = KV_DIM; NB = 4;  bxl = bx - 20; }

    gemm_core(Af + (size_t)by * Kt * 2048, Bf, Kt, NB, bxl, bias, C, N, by, As, Bs);
}

__global__ __launch_bounds__(256) void tf32_gemm_staged(
    const uint32_t* __restrict__ Af, const uint32_t* __restrict__ Bf,
    const float* __restrict__ bias, float* __restrict__ C,
    int M, int N, int K)
{
    extern __shared__ __align__(16) uint32_t smem[];
    uint32_t* As = smem;
    uint32_t* Bs = smem + 4 * 2048;
    const int Kt = K / 16;
    gemm_core(Af + (size_t)blockIdx.y * Kt * 2048, Bf, Kt, N / 128, blockIdx.x,
              bias, C, N, blockIdx.y, As, Bs);
}

// ---------------- fused per-head LayerNorm + RoPE (q and k, one launch) -----
__global__ void ln_rope_all(float* __restrict__ qb_, float* __restrict__ kb_,
                            const float* __restrict__ q_g, const float* __restrict__ q_b,
                            const float* __restrict__ k_g, const float* __restrict__ k_b)
{
    int row = blockIdx.x * blockDim.y + threadIdx.y;
    const int QROWS = SEQ * N_HEADS;
    const int TOT = QROWS + SEQ * N_KV;
    if (row >= TOT) return;

    float* buf; const float* gamma; const float* beta; int heads; int lrow;
    if (row < QROWS) { buf = qb_; gamma = q_g; beta = q_b; heads = N_HEADS; lrow = row; }
    else             { buf = kb_; gamma = k_g; beta = k_b; heads = N_KV;   lrow = row - QROWS; }

    int s = lrow / heads;
    int lane = threadIdx.x;

    float* p = buf + (size_t)lrow * HEAD_DIM;
    float x0 = p[lane];
    float x1 = p[lane + 32];

    float sum = x0 + x1;
    float sq  = x0 * x0 + x1 * x1;
#pragma unroll
    for (int o = 16; o > 0; o >>= 1) {
        sum += __shfl_xor_sync(0xFFFFFFFFu, sum, o);
        sq  += __shfl_xor_sync(0xFFFFFFFFu, sq,  o);
    }
    float mean = sum * (1.0f / 64.0f);
    float var  = sq * (1.0f / 64.0f) - mean * mean;
    float inv  = rsqrtf(var + 1e-5f);

    float y0 = (x0 - mean) * inv * gamma[lane]      + beta[lane];
    float y1 = (x1 - mean) * inv * gamma[lane + 32] + beta[lane + 32];

    float freq = powf(10000.0f, -(float)lane * (1.0f / 32.0f));
    float ang  = (float)s * freq;
    float c, sn;
    sincosf(ang, &sn, &c);

    p[lane]      = y0 * c - y1 * sn;
    p[lane + 32] = y1 * c + y0 * sn;
}

// ---------------- K/V -> fragment layout conversion (once per launch) -------
// grid (tiles=64, g=8, which: 0=K, 1=V), 128 threads.
// Output block stride 64 words (packed); same word mapping as the old in-loop
// staging, so the attention LDS indexing is unchanged except stride 66->64.
__global__ __launch_bounds__(128) void kv_frag_kernel(
    const float* __restrict__ k, const float* __restrict__ v,
    uint32_t* __restrict__ kfrag, uint32_t* __restrict__ vfrag)
{
    __shared__ __align__(16) uint32_t buf[2048];
    const int t = blockIdx.x;
    const int g = blockIdx.y;
    const int which = blockIdx.z;
    const int tid = threadIdx.x;

    const float* src = (which == 0 ? k : v) + g * HEAD_DIM;
#pragma unroll
    for (int i = 0; i < 4; i++) {
        int f4 = tid + i * 128;
        int row = f4 >> 4, c4 = (f4 & 15) * 4;
        float4 val = *(const float4*)(src + (size_t)(t * 32 + row) * KV_DIM + c4);
        if (which == 0) {
            int ntb = row >> 3, gidb = row & 7;
            int ksb = c4 >> 3, regb = (c4 & 4) >> 2;
            uint32_t* kd = &buf[(ntb * 8 + ksb) * 64 + gidb * 8 + regb];
            kd[0] = f2tf32(val.x); kd[2] = f2tf32(val.y);
            kd[4] = f2tf32(val.z); kd[6] = f2tf32(val.w);
        } else {
            int kj = row >> 3, r8 = row & 7;
            int tigv = r8 & 3, regv = r8 >> 2;
            float vals[4] = {val.x, val.y, val.z, val.w};
#pragma unroll
            for (int u = 0; u < 4; u++) {
                int c = c4 + u;
                int ntv = c >> 3, gidv = c & 7;
                buf[(ntv * 4 + kj) * 64 + gidv * 8 + tigv * 2 + regv] = f2tf32(vals[u]);
            }
        }
    }
    __syncthreads();
    uint32_t* dst = (which == 0 ? kfrag : vfrag) + ((size_t)g * 64 + t) * 2048;
#pragma unroll
    for (int j = 0; j < 4; j++)
        *(uint4*)(dst + j * 512 + tid * 4) = *(const uint4*)(buf + j * 512 + tid * 4);
}

// ============================================================================
// Tensor-core flash attention (tf32 mma, non-causal, GQA)
// K/V pre-converted to fragment-layout gmem -> mainloop is pure cp.async +
// LDS.64/LDS.128 + mma. 4-stage pipeline, 1 barrier per tile.
// ============================================================================
#define AT_BK 32
#define ATTN_SMEM_BYTES ((4 * 2048 * 2 + 4096) * 4)   // 80 KB

__global__ __launch_bounds__(128) void attn_mma_kernel(
    const float* __restrict__ q, const uint32_t* __restrict__ kfrag,
    const uint32_t* __restrict__ vfrag, uint32_t* __restrict__ o_frag)
{
    extern __shared__ __align__(16) uint32_t sm[];
    uint32_t* Kfs = sm;               // [4][2048]
    uint32_t* Vfs = sm + 4 * 2048;    // [4][2048]
    uint32_t* Pf  = sm + 8 * 2048;    // [8][512] A-frag

    const int h   = blockIdx.y;
    const int g   = h >> 2;
    const int q0  = blockIdx.x * 128;
    const int tid = threadIdx.x;
    const int w   = tid >> 5;      // 0..3
    const int lane = tid & 31;
    const int gid  = lane >> 2;
    const int tig  = lane & 3;

    // ---- Q fragments in registers ----
    uint32_t qf[2][8][4];
#pragma unroll
    for (int mt = 0; mt < 2; mt++) {
        const float* qp = q + (size_t)(q0 + w * 32 + mt * 16) * HIDDEN + h * HEAD_DIM;
#pragma unroll
        for (int ks = 0; ks < 8; ks++) {
            qf[mt][ks][0] = f2tf32(qp[(size_t)gid       * HIDDEN + ks * 8 + tig]);
            qf[mt][ks][1] = f2tf32(qp[(size_t)(gid + 8) * HIDDEN + ks * 8 + tig]);
            qf[mt][ks][2] = f2tf32(qp[(size_t)gid       * HIDDEN + ks * 8 + tig + 4]);
            qf[mt][ks][3] = f2tf32(qp[(size_t)(gid + 8) * HIDDEN + ks * 8 + tig + 4]);
        }
    }

    float o[2][8][4];
#pragma unroll
    for (int mt = 0; mt < 2; mt++)
#pragma unroll
        for (int nt = 0; nt < 8; nt++)
#pragma unroll
            for (int r = 0; r < 4; r++) o[mt][nt][r] = 0.f;
    float m[2][2] = {{-1e30f, -1e30f}, {-1e30f, -1e30f}};
    float l[2][2] = {{0.f, 0.f}, {0.f, 0.f}};

    const uint32_t* kg = kfrag + (size_t)g * 64 * 2048;
    const uint32_t* vg = vfrag + (size_t)g * 64 * 2048;
    const int NT = SEQ / AT_BK;   // 64

#define A_ISSUE(t_, s_)                                                       \
    do {                                                                      \
        if ((t_) < NT) {                                                      \
            const uint32_t* kgp = kg + (size_t)(t_) * 2048;                   \
            const uint32_t* vgp = vg + (size_t)(t_) * 2048;                   \
            _Pragma("unroll")                                                 \
            for (int j_ = 0; j_ < 4; j_++) {                                  \
                int off_ = j_ * 512 + tid * 4;                                \
                cp_async16(&Kfs[(s_) * 2048 + off_], kgp + off_);             \
                cp_async16(&Vfs[(s_) * 2048 + off_], vgp + off_);             \
            }                                                                 \
        }                                                                     \
        CP_COMMIT();                                                          \
    } while (0)

    A_ISSUE(0, 0);
    A_ISSUE(1, 1);
    A_ISSUE(2, 2);

    for (int t = 0; t < NT; t++) {
        const int s = t & 3;
        CP_WAIT2();
        __syncthreads();
        A_ISSUE(t + 3, (t + 3) & 3);

        const uint32_t* Ks = &Kfs[s * 2048];
        const uint32_t* Vs = &Vfs[s * 2048];

        // ---- QK^T: K b-frag = one LDS.64 per (ks,nt) ----
        float sc[2][4][4];
#pragma unroll
        for (int mt = 0; mt < 2; mt++)
#pragma unroll
            for (int nt = 0; nt < 4; nt++)
#pragma unroll
                for (int r = 0; r < 4; r++) sc[mt][nt][r] = 0.f;
#pragma unroll
        for (int ks = 0; ks < 8; ks++) {
#pragma unroll
            for (int nt = 0; nt < 4; nt++) {
                uint2 bb = *(const uint2*)&Ks[(nt * 8 + ks) * 64 + lane * 2];
                uint32_t br[2] = {bb.x, bb.y};
                mma_tf32(sc[0][nt], qf[0][ks], br);
                mma_tf32(sc[1][nt], qf[1][ks], br);
            }
        }

        // ---- online softmax per m-tile; P stored in A-frag layout ----
        const int r2  = 2 * (tig >> 1);
        const int ta0 = (2 * tig) & 3;
        const int ta1 = (2 * tig + 1) & 3;
#pragma unroll
        for (int mt = 0; mt < 2; mt++) {
#pragma unroll
            for (int nt = 0; nt < 4; nt++)
#pragma unroll
                for (int r = 0; r < 4; r++) sc[mt][nt][r] *= 0.125f;

            float mr0 = sc[mt][0][0], mr1 = sc[mt][0][2];
#pragma unroll
            for (int nt = 0; nt < 4; nt++) {
                mr0 = fmaxf(mr0, fmaxf(sc[mt][nt][0], sc[mt][nt][1]));
                mr1 = fmaxf(mr1, fmaxf(sc[mt][nt][2], sc[mt][nt][3]));
            }
            mr0 = fmaxf(mr0, __shfl_xor_sync(0xFFFFFFFFu, mr0, 1));
            mr0 = fmaxf(mr0, __shfl_xor_sync(0xFFFFFFFFu, mr0, 2));
            mr1 = fmaxf(mr1, __shfl_xor_sync(0xFFFFFFFFu, mr1, 1));
            mr1 = fmaxf(mr1, __shfl_xor_sync(0xFFFFFFFFu, mr1, 2));

            float mn0 = fmaxf(m[mt][0], mr0), mn1 = fmaxf(m[mt][1], mr1);
            float a0 = __expf(m[mt][0] - mn0), a1 = __expf(m[mt][1] - mn1);
            m[mt][0] = mn0; m[mt][1] = mn1;

            float lp0 = 0.f, lp1 = 0.f;
            uint32_t* Pw = &Pf[(w * 2 + mt) * 512];
#pragma unroll
            for (int nt = 0; nt < 4; nt++) {
                float p00 = __expf(sc[mt][nt][0] - mn0);
                float p01 = __expf(sc[mt][nt][1] - mn0);
                float p10 = __expf(sc[mt][nt][2] - mn1);
                float p11 = __expf(sc[mt][nt][3] - mn1);
                lp0 += p00 + p01;
                lp1 += p10 + p11;
                uint32_t* w0 = &Pw[(nt * 32 + gid * 4 + ta0) * 4 + r2];
                uint32_t* w1 = &Pw[(nt * 32 + gid * 4 + ta1) * 4 + r2];
                w0[0] = f2tf32(p00); w0[1] = f2tf32(p10);
                w1[0] = f2tf32(p01); w1[1] = f2tf32(p11);
            }
            lp0 += __shfl_xor_sync(0xFFFFFFFFu, lp0, 1);
            lp0 += __shfl_xor_sync(0xFFFFFFFFu, lp0, 2);
            lp1 += __shfl_xor_sync(0xFFFFFFFFu, lp1, 1);
            lp1 += __shfl_xor_sync(0xFFFFFFFFu, lp1, 2);
            l[mt][0] = l[mt][0] * a0 + lp0;
            l[mt][1] = l[mt][1] * a1 + lp1;

#pragma unroll
            for (int nt = 0; nt < 8; nt++) {
                o[mt][nt][0] *= a0; o[mt][nt][1] *= a0;
                o[mt][nt][2] *= a1; o[mt][nt][3] *= a1;
            }
        }
        __syncwarp();

        // ---- O += P @ V ; P a-frag LDS.128, V b-frag LDS.64 ----
#pragma unroll
        for (int kj = 0; kj < 4; kj++) {
            uint4 pa0 = *(const uint4*)&Pf[(w * 2 + 0) * 512 + (kj * 32 + lane) * 4];
            uint4 pa1 = *(const uint4*)&Pf[(w * 2 + 1) * 512 + (kj * 32 + lane) * 4];
            uint32_t a0[4] = {pa0.x, pa0.y, pa0.z, pa0.w};
            uint32_t a1[4] = {pa1.x, pa1.y, pa1.z, pa1.w};
#pragma unroll
            for (int nt = 0; nt < 8; nt++) {
                uint2 bb = *(const uint2*)&Vs[(nt * 4 + kj) * 64 + lane * 2];
                uint32_t br[2] = {bb.x, bb.y};
                mma_tf32(o[0][nt], a0, br);
                mma_tf32(o[1][nt], a1, br);
            }
        }
    }
#undef A_ISSUE

    // ---- write O directly into A-fragment layout for the Wo GEMM ----
    const int Kt = HIDDEN / 16;
    const int by = q0 >> 7;
    uint32_t* dstb = o_frag + (size_t)by * Kt * 2048;
    const int cc0 = 2 * tig;
    const int rhi = cc0 >> 2;
    const int t0 = gid * 4 + (cc0 & 3);
    const int t1 = gid * 4 + ((cc0 + 1) & 3);
#pragma unroll
    for (int mt = 0; mt < 2; mt++) {
        const float il0 = 1.0f / l[mt][0], il1 = 1.0f / l[mt][1];
        const int mt_g = w * 2 + mt;
#pragma unroll
        for (int nt = 0; nt < 8; nt++) {
            int kt = h * 4 + (nt >> 1);
            int ks = nt & 1;
            uint32_t* base = dstb + (size_t)kt * 2048 + (size_t)((mt_g * 2 + ks) * 32) * 4;
            base[t0 * 4 + 2 * rhi]     = f2tf32(o[mt][nt][0] * il0);
            base[t1 * 4 + 2 * rhi]     = f2tf32(o[mt][nt][1] * il0);
            base[t0 * 4 + 1 + 2 * rhi] = f2tf32(o[mt][nt][2] * il1);
            base[t1 * 4 + 1 + 2 * rhi] = f2tf32(o[mt][nt][3] * il1);
        }
    }
}

// ---------------- launch --------------------------------------------------
extern "C" void kernel_launch(void* const* d_in, const int* in_sizes, int n_in,
                              void* d_out, int out_size)
{
    const float* x   = (const float*)d_in[0];
    const float* Wq  = (const float*)d_in[1];
    const float* bq  = (const float*)d_in[2];
    const float* Wk  = (const float*)d_in[3];
    const float* bk  = (const float*)d_in[4];
    const float* Wv  = (const float*)d_in[5];
    const float* bv  = (const float*)d_in[6];
    const float* Wo  = (const float*)d_in[7];
    const float* bo  = (const float*)d_in[8];
    const float* q_g = (const float*)d_in[9];
    const float* q_b = (const float*)d_in[10];
    const float* k_g = (const float*)d_in[11];
    const float* k_b = (const float*)d_in[12];
    float* out = (float*)d_out;

    void *pq, *pk, *pv;
    void *pxa, *pwq, *pwk, *pwv, *pwo, *poa, *pkf, *pvf;
    cudaGetSymbolAddress(&pq, g_q);
    cudaGetSymbolAddress(&pk, g_k);
    cudaGetSymbolAddress(&pv, g_v);
    cudaGetSymbolAddress(&pxa, g_xa);
    cudaGetSymbolAddress(&pwq, g_wq);
    cudaGetSymbolAddress(&pwk, g_wk);
    cudaGetSymbolAddress(&pwv, g_wv);
    cudaGetSymbolAddress(&pwo, g_wo);
    cudaGetSymbolAddress(&poa, g_oa);
    cudaGetSymbolAddress(&pkf, g_kf);
    cudaGetSymbolAddress(&pvf, g_vf);
    float* fq = (float*)pq;
    float* fk = (float*)pk;
    float* fv = (float*)pv;
    uint32_t* xa = (uint32_t*)pxa;
    uint32_t* wqf = (uint32_t*)pwq;
    uint32_t* wkf = (uint32_t*)pwk;
    uint32_t* wvf = (uint32_t*)pwv;
    uint32_t* wof = (uint32_t*)pwo;
    uint32_t* oa = (uint32_t*)poa;
    uint32_t* kfr = (uint32_t*)pkf;
    uint32_t* vfr = (uint32_t*)pvf;

    const int GEMM_SMEM = 16 * 2048 * 4;   // 64 KB
    cudaFuncSetAttribute(tf32_gemm_qkv,
                         cudaFuncAttributeMaxDynamicSharedMemorySize, GEMM_SMEM);
    cudaFuncSetAttribute(tf32_gemm_staged,
                         cudaFuncAttributeMaxDynamicSharedMemorySize, GEMM_SMEM);
    cudaFuncSetAttribute(attn_mma_kernel,
                         cudaFuncAttributeMaxDynamicSharedMemorySize, ATTN_SMEM_BYTES);

    // one combined shuffle launch (x + all 4 weights)
    shuffle_all_kernel<<<3584, 256>>>(x, Wq, Wk, Wv, Wo, xa, wqf, wkf, wvf, wof);

    // fused Q/K/V projections
    {
        dim3 grid(24, SEQ / 128);
        tf32_gemm_qkv<<<grid, 256, GEMM_SMEM>>>(xa, wqf, wkf, wvf,
                                                bq, bk, bv, fq, fk, fv);
    }

    // per-head LN + RoPE (q and k in one launch)
    {
        dim3 blk(32, 4);
        int rows = SEQ * N_HEADS + SEQ * N_KV;
        ln_rope_all<<<(rows + 3) / 4, blk>>>(fq, fk, q_g, q_b, k_g, k_b);
    }

    // K/V -> fragment layout (once)
    {
        dim3 grid(SEQ / 32, N_KV, 2);
        kv_frag_kernel<<<grid, 128>>>(fk, fv, kfr, vfr);
    }

    // attention (BQ=128, 4 warps x m32, cp.async KV pipeline)
    {
        dim3 grid(SEQ / 128, N_HEADS);
        attn_mma_kernel<<<grid, 128, ATTN_SMEM_BYTES>>>(fq, kfr, vfr, oa);
    }

    // output projection
    {
        dim3 grid(HIDDEN / 128, SEQ / 128);
        tf32_gemm_staged<<<grid, 256, GEMM_SMEM>>>(oa, wof, bo, out, SEQ, HIDDEN, HIDDEN);
    }
}

// round 12
// speedup vs baseline: 1.1141x; 1.0249x over previous
#include <cuda_runtime.h>
#include <cuda_bf16.h>
#include <math.h>
#include <stdint.h>

// ---------------- problem constants ----------------
#define SEQ      2048
#define HIDDEN   2048
#define N_HEADS  32
#define N_KV     8
#define HEAD_DIM 64
#define KV_DIM   (N_KV * HEAD_DIM)   // 512

// ---------------- scratch ----------------
__device__ float g_q[SEQ * HIDDEN];
__device__ float g_k[SEQ * KV_DIM];
__device__ float g_v[SEQ * KV_DIM];

// fragment-staged GEMM operands (tf32 bits). Tile = 2048 words (8KB).
__device__ uint32_t g_xa[(SEQ / 128) * (HIDDEN / 16) * 2048];
__device__ uint32_t g_wq[(HIDDEN / 16) * (HIDDEN / 128) * 2048];
__device__ uint32_t g_wk[(HIDDEN / 16) * (KV_DIM / 128) * 2048];
__device__ uint32_t g_wv[(HIDDEN / 16) * (KV_DIM / 128) * 2048];
__device__ uint32_t g_wo[(HIDDEN / 16) * (HIDDEN / 128) * 2048];
__device__ uint32_t g_oa[(SEQ / 128) * (HIDDEN / 16) * 2048];

// fragment-staged K/V for attention: [g(8)][tile(64)][2048 words]
__device__ uint32_t g_kf[N_KV * (SEQ / 32) * 2048];   // 4 MB
__device__ uint32_t g_vf[N_KV * (SEQ / 32) * 2048];   // 4 MB

__device__ __forceinline__ uint32_t f2tf32(float x) {
    uint32_t r;
    asm("cvt.rna.tf32.f32 %0, %1;" : "=r"(r) : "f"(x));
    return r;
}

__device__ __forceinline__ void mma_tf32(float c[4], const uint32_t a[4], const uint32_t b[2]) {
    asm volatile(
        "mma.sync.aligned.m16n8k8.row.col.f32.tf32.tf32.f32 "
        "{%0,%1,%2,%3},{%4,%5,%6,%7},{%8,%9},{%0,%1,%2,%3};"
        : "+f"(c[0]), "+f"(c[1]), "+f"(c[2]), "+f"(c[3])
        : "r"(a[0]), "r"(a[1]), "r"(a[2]), "r"(a[3]), "r"(b[0]), "r"(b[1]));
}

__device__ __forceinline__ uint32_t smem_u32(const void* p) {
    return (uint32_t)__cvta_generic_to_shared(p);
}
__device__ __forceinline__ void cp_async16(void* smem, const void* gmem) {
    asm volatile("cp.async.cg.shared.global [%0], [%1], 16;"
                 :: "r"(smem_u32(smem)), "l"(gmem));
}
#define CP_COMMIT() asm volatile("cp.async.commit_group;")
#define CP_WAIT2()  asm volatile("cp.async.wait_group 2;")

// ---------------- fragment scatter maps ------------------------------------
__device__ __forceinline__ void stage_a(uint32_t* dst, float4 v, int lin) {
    const int arow = lin >> 2;
    const int cbase = (lin & 3) * 4;
    float vv[4] = {v.x, v.y, v.z, v.w};
#pragma unroll
    for (int u = 0; u < 4; u++) {
        int j  = cbase + u;
        int mt = arow >> 4, rr = arow & 15;
        int ks = j >> 3,    cc = j & 7;
        int t   = (rr & 7) * 4 + (cc & 3);
        int reg = (rr >> 3) + 2 * (cc >> 2);
        dst[((mt * 2 + ks) * 32 + t) * 4 + reg] = f2tf32(vv[u]);
    }
}
__device__ __forceinline__ void stage_b(uint32_t* dst, float4 v, int lin) {
    const int brow = lin >> 5;
    const int cbase = (lin & 31) * 4;
    float vv[4] = {v.x, v.y, v.z, v.w};
#pragma unroll
    for (int u = 0; u < 4; u++) {
        int j  = cbase + u;
        int nt = j >> 3, cc = j & 7;
        int ks = brow >> 3, kk = brow & 7;
        int t   = cc * 4 + (kk & 3);
        int reg = kk >> 2;
        dst[((nt * 2 + ks) * 32 + t) * 2 + reg] = f2tf32(vv[u]);
    }
}

// ---------------- combined shuffle (all operands, one launch) ---------------
__device__ __forceinline__ void shuffle_a_body(
    const float* __restrict__ A, uint32_t* __restrict__ Af,
    int K, int ktp, int by, uint32_t* buf)
{
    const int kt0 = ktp * 2;
    const int Kt = K / 16;
    const int tid = threadIdx.x;
    const int row0 = tid >> 2, c40 = (tid & 3) * 4;
    const int lin1 = 256 + tid;
    const int row1 = lin1 >> 2, c41 = (lin1 & 3) * 4;
    const float* Ab = A + (size_t)(by * 128) * K;

    float4 v[2][2];
#pragma unroll
    for (int t = 0; t < 2; t++) {
        const float* base = Ab + (kt0 + t) * 16;
        v[t][0] = *(const float4*)(base + (size_t)row0 * K + c40);
        v[t][1] = *(const float4*)(base + (size_t)row1 * K + c41);
    }
#pragma unroll
    for (int t = 0; t < 2; t++) {
        stage_a(buf + t * 2048, v[t][0], tid);
        stage_a(buf + t * 2048, v[t][1], lin1);
    }
    __syncthreads();
#pragma unroll
    for (int t = 0; t < 2; t++) {
        uint32_t* dst = Af + ((size_t)by * Kt + kt0 + t) * 2048;
        *(uint4*)(dst + tid * 4)        = *(const uint4*)(buf + t * 2048 + tid * 4);
        *(uint4*)(dst + 1024 + tid * 4) = *(const uint4*)(buf + t * 2048 + 1024 + tid * 4);
    }
}

__device__ __forceinline__ void shuffle_b_body(
    const float* __restrict__ B, uint32_t* __restrict__ Bf,
    int K, int N, int bx, int ktp, uint32_t* buf)
{
    const int kt0 = ktp * 2;
    const int NB = N / 128;
    const int tid = threadIdx.x;
    const int brow0 = tid >> 5, c40 = (tid & 31) * 4;
    const int lin1 = 256 + tid;
    const int brow1 = lin1 >> 5, c41 = (lin1 & 31) * 4;

    float4 v[2][2];
#pragma unroll
    for (int t = 0; t < 2; t++) {
        const float* Bb = B + (size_t)((kt0 + t) * 16) * N + bx * 128;
        v[t][0] = *(const float4*)(Bb + (size_t)brow0 * N + c40);
        v[t][1] = *(const float4*)(Bb + (size_t)brow1 * N + c41);
    }
#pragma unroll
    for (int t = 0; t < 2; t++) {
        stage_b(buf + t * 2048, v[t][0], tid);
        stage_b(buf + t * 2048, v[t][1], lin1);
    }
    __syncthreads();
#pragma unroll
    for (int t = 0; t < 2; t++) {
        uint32_t* dst = Bf + ((size_t)(kt0 + t) * NB + bx) * 2048;
        *(uint4*)(dst + tid * 4)        = *(const uint4*)(buf + t * 2048 + tid * 4);
        *(uint4*)(dst + 1024 + tid * 4) = *(const uint4*)(buf + t * 2048 + 1024 + tid * 4);
    }
}

__global__ __launch_bounds__(256) void shuffle_all_kernel(
    const float* __restrict__ x,
    const float* __restrict__ Wq, const float* __restrict__ Wk,
    const float* __restrict__ Wv, const float* __restrict__ Wo,
    uint32_t* __restrict__ xa, uint32_t* __restrict__ wq,
    uint32_t* __restrict__ wk, uint32_t* __restrict__ wv,
    uint32_t* __restrict__ wo)
{
    __shared__ __align__(16) uint32_t buf[2 * 2048];
    int b = blockIdx.x;
    if (b < 1024) {
        shuffle_a_body(x, xa, HIDDEN, b & 63, b >> 6, buf);
    } else if (b < 2048) {
        b -= 1024;
        shuffle_b_body(Wq, wq, HIDDEN, HIDDEN, b & 15, b >> 4, buf);
    } else if (b < 2304) {
        b -= 2048;
        shuffle_b_body(Wk, wk, HIDDEN, KV_DIM, b & 3, b >> 2, buf);
    } else if (b < 2560) {
        b -= 2304;
        shuffle_b_body(Wv, wv, HIDDEN, KV_DIM, b & 3, b >> 2, buf);
    } else {
        b -= 2560;
        shuffle_b_body(Wo, wo, HIDDEN, HIDDEN, b & 15, b >> 4, buf);
    }
}

// ---------------- GEMM core: 4-stage cp.async, 1 barrier/iter ---------------
__device__ __forceinline__ void gemm_core(
    const uint32_t* __restrict__ Abase,
    const uint32_t* __restrict__ Bf,
    int Kt, int NB, int bxl,
    const float* __restrict__ bias, float* __restrict__ C, int N,
    int by, uint32_t* As, uint32_t* Bs)
{
    const int tid  = threadIdx.x;
    const int lane = tid & 31;
    const int wid  = tid >> 5;
    const int warp_m = wid >> 2;
    const int warp_n = wid & 3;

    float c[4][4][4];
#pragma unroll
    for (int i = 0; i < 4; i++)
#pragma unroll
        for (int j = 0; j < 4; j++)
#pragma unroll
            for (int r = 0; r < 4; r++) c[i][j][r] = 0.f;

    const int o0 = tid * 4;
    const int o1 = 1024 + tid * 4;

#define G_ISSUE(kt_, s_)                                                     \
    do {                                                                     \
        if ((kt_) < Kt) {                                                    \
            const uint32_t* ag = Abase + (size_t)(kt_) * 2048;               \
            const uint32_t* bg = Bf + ((size_t)(kt_) * NB + bxl) * 2048;     \
            cp_async16(&As[(s_) * 2048 + o0], ag + o0);                      \
            cp_async16(&As[(s_) * 2048 + o1], ag + o1);                      \
            cp_async16(&Bs[(s_) * 2048 + o0], bg + o0);                      \
            cp_async16(&Bs[(s_) * 2048 + o1], bg + o1);                      \
        }                                                                    \
        CP_COMMIT();                                                         \
    } while (0)

    G_ISSUE(0, 0);
    G_ISSUE(1, 1);
    G_ISSUE(2, 2);

    for (int kt = 0; kt < Kt; kt++) {
        const int s = kt & 3;
        CP_WAIT2();
        __syncthreads();
        G_ISSUE(kt + 3, (kt + 3) & 3);

        const uint32_t* Ass = &As[s * 2048];
        const uint32_t* Bss = &Bs[s * 2048];
#pragma unroll
        for (int ks = 0; ks < 2; ks++) {
            uint4 a[4];
            uint2 b[4];
#pragma unroll
            for (int mt = 0; mt < 4; mt++)
                a[mt] = *(const uint4*)&Ass[(((warp_m * 4 + mt) * 2 + ks) * 32 + lane) * 4];
#pragma unroll
            for (int nt = 0; nt < 4; nt++)
                b[nt] = *(const uint2*)&Bss[(((warp_n * 4 + nt) * 2 + ks) * 32 + lane) * 2];
#pragma unroll
            for (int mt = 0; mt < 4; mt++)
#pragma unroll
                for (int nt = 0; nt < 4; nt++) {
                    uint32_t ar[4] = {a[mt].x, a[mt].y, a[mt].z, a[mt].w};
                    uint32_t br[2] = {b[nt].x, b[nt].y};
                    mma_tf32(c[mt][nt], ar, br);
                }
        }
    }
#undef G_ISSUE

#pragma unroll
    for (int mt = 0; mt < 4; mt++) {
        int gr = by * 128 + warp_m * 64 + mt * 16 + (lane >> 2);
#pragma unroll
        for (int nt = 0; nt < 4; nt++) {
            int gc = bxl * 128 + warp_n * 32 + nt * 8 + (lane & 3) * 2;
            float b0 = bias[gc], b1 = bias[gc + 1];
            float2 r0 = {c[mt][nt][0] + b0, c[mt][nt][1] + b1};
            float2 r1 = {c[mt][nt][2] + b0, c[mt][nt][3] + b1};
            *(float2*)(C + (size_t)gr * N + gc) = r0;
            *(float2*)(C + (size_t)(gr + 8) * N + gc) = r1;
        }
    }
}

__global__ __launch_bounds__(256) void tf32_gemm_qkv(
    const uint32_t* __restrict__ Af,
    const uint32_t* __restrict__ Bq, const uint32_t* __restrict__ Bk,
    const uint32_t* __restrict__ Bv,
    const float* __restrict__ bq, const float* __restrict__ bk,
    const float* __restrict__ bv,
    float* __restrict__ cq, float* __restrict__ ck, float* __restrict__ cv)
{
    extern __shared__ __align__(16) uint32_t smem[];
    uint32_t* As = smem;
    uint32_t* Bs = smem + 4 * 2048;

    const int bx = blockIdx.x;
    const int by = blockIdx.y;
    const int Kt = HIDDEN / 16;

    const uint32_t* Bf;
    const float* bias;
    float* C;
    int N, NB, bxl;
    if (bx < 16)      { Bf = Bq; bias = bq; C = cq; N = HIDDEN; NB = 16; bxl = bx; }
    else if (bx < 20) { Bf = Bk; bias = bk; C = ck; N = KV_DIM; NB = 4;  bxl = bx - 16; }
    else              { Bf = Bv; bias = bv; C = cv; N = KV_DIM; NB = 4;  bxl = bx - 20; }

    gemm_core(Af + (size_t)by * Kt * 2048, Bf, Kt, NB, bxl, bias, C, N, by, As, Bs);
}

__global__ __launch_bounds__(256) void tf32_gemm_staged(
    const uint32_t* __restrict__ Af, const uint32_t* __restrict__ Bf,
    const float* __restrict__ bias, float* __restrict__ C,
    int M, int N, int K)
{
    extern __shared__ __align__(16) uint32_t smem[];
    uint32_t* As = smem;
    uint32_t* Bs = smem + 4 * 2048;
    const int Kt = K / 16;
    gemm_core(Af + (size_t)blockIdx.y * Kt * 2048, Bf, Kt, N / 128, blockIdx.x,
              bias, C, N, blockIdx.y, As, Bs);
}

// ---------------- fused per-head LayerNorm + RoPE (q and k, one launch) -----
__global__ void ln_rope_all(float* __restrict__ qb_, float* __restrict__ kb_,
                            const float* __restrict__ q_g, const float* __restrict__ q_b,
                            const float* __restrict__ k_g, const float* __restrict__ k_b)
{
    int row = blockIdx.x * blockDim.y + threadIdx.y;
    const int QROWS = SEQ * N_HEADS;
    const int TOT = QROWS + SEQ * N_KV;
    if (row >= TOT) return;

    float* buf; const float* gamma; const float* beta; int heads; int lrow;
    if (row < QROWS) { buf = qb_; gamma = q_g; beta = q_b; heads = N_HEADS; lrow = row; }
    else             { buf = kb_; gamma = k_g; beta = k_b; heads = N_KV;   lrow = row - QROWS; }

    int s = lrow / heads;
    int lane = threadIdx.x;

    float* p = buf + (size_t)lrow * HEAD_DIM;
    float x0 = p[lane];
    float x1 = p[lane + 32];

    float sum = x0 + x1;
    float sq  = x0 * x0 + x1 * x1;
#pragma unroll
    for (int o = 16; o > 0; o >>= 1) {
        sum += __shfl_xor_sync(0xFFFFFFFFu, sum, o);
        sq  += __shfl_xor_sync(0xFFFFFFFFu, sq,  o);
    }
    float mean = sum * (1.0f / 64.0f);
    float var  = sq * (1.0f / 64.0f) - mean * mean;
    float inv  = rsqrtf(var + 1e-5f);

    float y0 = (x0 - mean) * inv * gamma[lane]      + beta[lane];
    float y1 = (x1 - mean) * inv * gamma[lane + 32] + beta[lane + 32];

    float freq = powf(10000.0f, -(float)lane * (1.0f / 32.0f));
    float ang  = (float)s * freq;
    float c, sn;
    sincosf(ang, &sn, &c);

    p[lane]      = y0 * c - y1 * sn;
    p[lane + 32] = y1 * c + y0 * sn;
}

// ---------------- K/V -> fragment layout conversion (once per launch) -------
__global__ __launch_bounds__(128) void kv_frag_kernel(
    const float* __restrict__ k, const float* __restrict__ v,
    uint32_t* __restrict__ kfrag, uint32_t* __restrict__ vfrag)
{
    __shared__ __align__(16) uint32_t buf[2048];
    const int t = blockIdx.x;
    const int g = blockIdx.y;
    const int which = blockIdx.z;
    const int tid = threadIdx.x;

    const float* src = (which == 0 ? k : v) + g * HEAD_DIM;
#pragma unroll
    for (int i = 0; i < 4; i++) {
        int f4 = tid + i * 128;
        int row = f4 >> 4, c4 = (f4 & 15) * 4;
        float4 val = *(const float4*)(src + (size_t)(t * 32 + row) * KV_DIM + c4);
        if (which == 0) {
            int ntb = row >> 3, gidb = row & 7;
            int ksb = c4 >> 3, regb = (c4 & 4) >> 2;
            uint32_t* kd = &buf[(ntb * 8 + ksb) * 64 + gidb * 8 + regb];
            kd[0] = f2tf32(val.x); kd[2] = f2tf32(val.y);
            kd[4] = f2tf32(val.z); kd[6] = f2tf32(val.w);
        } else {
            int kj = row >> 3, r8 = row & 7;
            int tigv = r8 & 3, regv = r8 >> 2;
            float vals[4] = {val.x, val.y, val.z, val.w};
#pragma unroll
            for (int u = 0; u < 4; u++) {
                int c = c4 + u;
                int ntv = c >> 3, gidv = c & 7;
                buf[(ntv * 4 + kj) * 64 + gidv * 8 + tigv * 2 + regv] = f2tf32(vals[u]);
            }
        }
    }
    __syncthreads();
    uint32_t* dst = (which == 0 ? kfrag : vfrag) + ((size_t)g * 64 + t) * 2048;
#pragma unroll
    for (int j = 0; j < 4; j++)
        *(uint4*)(dst + j * 512 + tid * 4) = *(const uint4*)(buf + j * 512 + tid * 4);
}

// ============================================================================
// Tensor-core flash attention (tf32 mma, non-causal, GQA)
// Static-shift softmax: post-LN rows have norm exactly 8, so |score|<=8;
// p = exp(s - 24) is safe (shift-invariant softmax). No running max, no
// rescale, l reduced once after the mainloop.
// ============================================================================
#define AT_BK 32
#define SOFTMAX_SHIFT 24.0f
#define ATTN_SMEM_BYTES ((4 * 2048 * 2 + 4096) * 4)   // 80 KB

__global__ __launch_bounds__(128) void attn_mma_kernel(
    const float* __restrict__ q, const uint32_t* __restrict__ kfrag,
    const uint32_t* __restrict__ vfrag, uint32_t* __restrict__ o_frag)
{
    extern __shared__ __align__(16) uint32_t sm[];
    uint32_t* Kfs = sm;               // [4][2048]
    uint32_t* Vfs = sm + 4 * 2048;    // [4][2048]
    uint32_t* Pf  = sm + 8 * 2048;    // [8][512] A-frag

    const int h   = blockIdx.y;
    const int g   = h >> 2;
    const int q0  = blockIdx.x * 128;
    const int tid = threadIdx.x;
    const int w   = tid >> 5;      // 0..3
    const int lane = tid & 31;
    const int gid  = lane >> 2;
    const int tig  = lane & 3;

    // ---- Q fragments in registers ----
    uint32_t qf[2][8][4];
#pragma unroll
    for (int mt = 0; mt < 2; mt++) {
        const float* qp = q + (size_t)(q0 + w * 32 + mt * 16) * HIDDEN + h * HEAD_DIM;
#pragma unroll
        for (int ks = 0; ks < 8; ks++) {
            qf[mt][ks][0] = f2tf32(qp[(size_t)gid       * HIDDEN + ks * 8 + tig]);
            qf[mt][ks][1] = f2tf32(qp[(size_t)(gid + 8) * HIDDEN + ks * 8 + tig]);
            qf[mt][ks][2] = f2tf32(qp[(size_t)gid       * HIDDEN + ks * 8 + tig + 4]);
            qf[mt][ks][3] = f2tf32(qp[(size_t)(gid + 8) * HIDDEN + ks * 8 + tig + 4]);
        }
    }

    float o[2][8][4];
#pragma unroll
    for (int mt = 0; mt < 2; mt++)
#pragma unroll
        for (int nt = 0; nt < 8; nt++)
#pragma unroll
            for (int r = 0; r < 4; r++) o[mt][nt][r] = 0.f;
    float l[2][2] = {{0.f, 0.f}, {0.f, 0.f}};   // per-thread partials

    const uint32_t* kg = kfrag + (size_t)g * 64 * 2048;
    const uint32_t* vg = vfrag + (size_t)g * 64 * 2048;
    const int NT = SEQ / AT_BK;   // 64

#define A_ISSUE(t_, s_)                                                       \
    do {                                                                      \
        if ((t_) < NT) {                                                      \
            const uint32_t* kgp = kg + (size_t)(t_) * 2048;                   \
            const uint32_t* vgp = vg + (size_t)(t_) * 2048;                   \
            _Pragma("unroll")                                                 \
            for (int j_ = 0; j_ < 4; j_++) {                                  \
                int off_ = j_ * 512 + tid * 4;                                \
                cp_async16(&Kfs[(s_) * 2048 + off_], kgp + off_);             \
                cp_async16(&Vfs[(s_) * 2048 + off_], vgp + off_);             \
            }                                                                 \
        }                                                                     \
        CP_COMMIT();                                                          \
    } while (0)

    A_ISSUE(0, 0);
    A_ISSUE(1, 1);
    A_ISSUE(2, 2);

    const int r2  = 2 * (tig >> 1);
    const int ta0 = (2 * tig) & 3;
    const int ta1 = (2 * tig + 1) & 3;

    for (int t = 0; t < NT; t++) {
        const int s = t & 3;
        CP_WAIT2();
        __syncthreads();
        A_ISSUE(t + 3, (t + 3) & 3);

        const uint32_t* Ks = &Kfs[s * 2048];
        const uint32_t* Vs = &Vfs[s * 2048];

        // ---- QK^T ----
        float sc[2][4][4];
#pragma unroll
        for (int mt = 0; mt < 2; mt++)
#pragma unroll
            for (int nt = 0; nt < 4; nt++)
#pragma unroll
                for (int r = 0; r < 4; r++) sc[mt][nt][r] = 0.f;
#pragma unroll
        for (int ks = 0; ks < 8; ks++) {
#pragma unroll
            for (int nt = 0; nt < 4; nt++) {
                uint2 bb = *(const uint2*)&Ks[(nt * 8 + ks) * 64 + lane * 2];
                uint32_t br[2] = {bb.x, bb.y};
                mma_tf32(sc[0][nt], qf[0][ks], br);
                mma_tf32(sc[1][nt], qf[1][ks], br);
            }
        }

        // ---- static-shift softmax: p = exp(s/8 - SHIFT) ----
#pragma unroll
        for (int mt = 0; mt < 2; mt++) {
            uint32_t* Pw = &Pf[(w * 2 + mt) * 512];
#pragma unroll
            for (int nt = 0; nt < 4; nt++) {
                float p00 = __expf(fmaf(sc[mt][nt][0], 0.125f, -SOFTMAX_SHIFT));
                float p01 = __expf(fmaf(sc[mt][nt][1], 0.125f, -SOFTMAX_SHIFT));
                float p10 = __expf(fmaf(sc[mt][nt][2], 0.125f, -SOFTMAX_SHIFT));
                float p11 = __expf(fmaf(sc[mt][nt][3], 0.125f, -SOFTMAX_SHIFT));
                l[mt][0] += p00 + p01;
                l[mt][1] += p10 + p11;
                uint32_t* w0 = &Pw[(nt * 32 + gid * 4 + ta0) * 4 + r2];
                uint32_t* w1 = &Pw[(nt * 32 + gid * 4 + ta1) * 4 + r2];
                w0[0] = f2tf32(p00); w0[1] = f2tf32(p10);
                w1[0] = f2tf32(p01); w1[1] = f2tf32(p11);
            }
        }
        __syncwarp();

        // ---- O += P @ V ----
#pragma unroll
        for (int kj = 0; kj < 4; kj++) {
            uint4 pa0 = *(const uint4*)&Pf[(w * 2 + 0) * 512 + (kj * 32 + lane) * 4];
            uint4 pa1 = *(const uint4*)&Pf[(w * 2 + 1) * 512 + (kj * 32 + lane) * 4];
            uint32_t a0[4] = {pa0.x, pa0.y, pa0.z, pa0.w};
            uint32_t a1[4] = {pa1.x, pa1.y, pa1.z, pa1.w};
#pragma unroll
            for (int nt = 0; nt < 8; nt++) {
                uint2 bb = *(const uint2*)&Vs[(nt * 4 + kj) * 64 + lane * 2];
                uint32_t br[2] = {bb.x, bb.y};
                mma_tf32(o[0][nt], a0, br);
                mma_tf32(o[1][nt], a1, br);
            }
        }
    }
#undef A_ISSUE

    // ---- reduce l across the quad (once) ----
#pragma unroll
    for (int mt = 0; mt < 2; mt++) {
        l[mt][0] += __shfl_xor_sync(0xFFFFFFFFu, l[mt][0], 1);
        l[mt][0] += __shfl_xor_sync(0xFFFFFFFFu, l[mt][0], 2);
        l[mt][1] += __shfl_xor_sync(0xFFFFFFFFu, l[mt][1], 1);
        l[mt][1] += __shfl_xor_sync(0xFFFFFFFFu, l[mt][1], 2);
    }

    // ---- write O directly into A-fragment layout for the Wo GEMM ----
    const int Kt = HIDDEN / 16;
    const int by = q0 >> 7;
    uint32_t* dstb = o_frag + (size_t)by * Kt * 2048;
    const int cc0 = 2 * tig;
    const int rhi = cc0 >> 2;
    const int t0 = gid * 4 + (cc0 & 3);
    const int t1 = gid * 4 + ((cc0 + 1) & 3);
#pragma unroll
    for (int mt = 0; mt < 2; mt++) {
        const float il0 = 1.0f / l[mt][0], il1 = 1.0f / l[mt][1];
        const int mt_g = w * 2 + mt;
#pragma unroll
        for (int nt = 0; nt < 8; nt++) {
            int kt = h * 4 + (nt >> 1);
            int ks = nt & 1;
            uint32_t* base = dstb + (size_t)kt * 2048 + (size_t)((mt_g * 2 + ks) * 32) * 4;
            base[t0 * 4 + 2 * rhi]     = f2tf32(o[mt][nt][0] * il0);
            base[t1 * 4 + 2 * rhi]     = f2tf32(o[mt][nt][1] * il0);
            base[t0 * 4 + 1 + 2 * rhi] = f2tf32(o[mt][nt][2] * il1);
            base[t1 * 4 + 1 + 2 * rhi] = f2tf32(o[mt][nt][3] * il1);
        }
    }
}

// ---------------- launch --------------------------------------------------
extern "C" void kernel_launch(void* const* d_in, const int* in_sizes, int n_in,
                              void* d_out, int out_size)
{
    const float* x   = (const float*)d_in[0];
    const float* Wq  = (const float*)d_in[1];
    const float* bq  = (const float*)d_in[2];
    const float* Wk  = (const float*)d_in[3];
    const float* bk  = (const float*)d_in[4];
    const float* Wv  = (const float*)d_in[5];
    const float* bv  = (const float*)d_in[6];
    const float* Wo  = (const float*)d_in[7];
    const float* bo  = (const float*)d_in[8];
    const float* q_g = (const float*)d_in[9];
    const float* q_b = (const float*)d_in[10];
    const float* k_g = (const float*)d_in[11];
    const float* k_b = (const float*)d_in[12];
    float* out = (float*)d_out;

    void *pq, *pk, *pv;
    void *pxa, *pwq, *pwk, *pwv, *pwo, *poa, *pkf, *pvf;
    cudaGetSymbolAddress(&pq, g_q);
    cudaGetSymbolAddress(&pk, g_k);
    cudaGetSymbolAddress(&pv, g_v);
    cudaGetSymbolAddress(&pxa, g_xa);
    cudaGetSymbolAddress(&pwq, g_wq);
    cudaGetSymbolAddress(&pwk, g_wk);
    cudaGetSymbolAddress(&pwv, g_wv);
    cudaGetSymbolAddress(&pwo, g_wo);
    cudaGetSymbolAddress(&poa, g_oa);
    cudaGetSymbolAddress(&pkf, g_kf);
    cudaGetSymbolAddress(&pvf, g_vf);
    float* fq = (float*)pq;
    float* fk = (float*)pk;
    float* fv = (float*)pv;
    uint32_t* xa = (uint32_t*)pxa;
    uint32_t* wqf = (uint32_t*)pwq;
    uint32_t* wkf = (uint32_t*)pwk;
    uint32_t* wvf = (uint32_t*)pwv;
    uint32_t* wof = (uint32_t*)pwo;
    uint32_t* oa = (uint32_t*)poa;
    uint32_t* kfr = (uint32_t*)pkf;
    uint32_t* vfr = (uint32_t*)pvf;

    const int GEMM_SMEM = 16 * 2048 * 4;   // 64 KB
    cudaFuncSetAttribute(tf32_gemm_qkv,
                         cudaFuncAttributeMaxDynamicSharedMemorySize, GEMM_SMEM);
    cudaFuncSetAttribute(tf32_gemm_staged,
                         cudaFuncAttributeMaxDynamicSharedMemorySize, GEMM_SMEM);
    cudaFuncSetAttribute(attn_mma_kernel,
                         cudaFuncAttributeMaxDynamicSharedMemorySize, ATTN_SMEM_BYTES);

    // one combined shuffle launch (x + all 4 weights)
    shuffle_all_kernel<<<3584, 256>>>(x, Wq, Wk, Wv, Wo, xa, wqf, wkf, wvf, wof);

    // fused Q/K/V projections
    {
        dim3 grid(24, SEQ / 128);
        tf32_gemm_qkv<<<grid, 256, GEMM_SMEM>>>(xa, wqf, wkf, wvf,
                                                bq, bk, bv, fq, fk, fv);
    }

    // per-head LN + RoPE (q and k in one launch)
    {
        dim3 blk(32, 4);
        int rows = SEQ * N_HEADS + SEQ * N_KV;
        ln_rope_all<<<(rows + 3) / 4, blk>>>(fq, fk, q_g, q_b, k_g, k_b);
    }

    // K/V -> fragment layout (once)
    {
        dim3 grid(SEQ / 32, N_KV, 2);
        kv_frag_kernel<<<grid, 128>>>(fk, fv, kfr, vfr);
    }

    // attention (BQ=128, 4 warps x m32, static-shift softmax)
    {
        dim3 grid(SEQ / 128, N_HEADS);
        attn_mma_kernel<<<grid, 128, ATTN_SMEM_BYTES>>>(fq, kfr, vfr, oa);
    }

    // output projection
    {
        dim3 grid(HIDDEN / 128, SEQ / 128);
        tf32_gemm_staged<<<grid, 256, GEMM_SMEM>>>(oa, wof, bo, out, SEQ, HIDDEN, HIDDEN);
    }
}

// round 13
// speedup vs baseline: 1.1571x; 1.0385x over previous
#include <cuda_runtime.h>
#include <cuda_bf16.h>
#include <math.h>
#include <stdint.h>

// ---------------- problem constants ----------------
#define SEQ      2048
#define HIDDEN   2048
#define N_HEADS  32
#define N_KV     8
#define HEAD_DIM 64
#define KV_DIM   (N_KV * HEAD_DIM)   // 512

// ---------------- scratch ----------------
__device__ float g_q[SEQ * HIDDEN];
__device__ float g_k[SEQ * KV_DIM];
__device__ float g_v[SEQ * KV_DIM];

// fragment-staged GEMM operands (tf32 bits). Tile = 2048 words (8KB).
__device__ uint32_t g_xa[(SEQ / 128) * (HIDDEN / 16) * 2048];
__device__ uint32_t g_wq[(HIDDEN / 16) * (HIDDEN / 128) * 2048];
__device__ uint32_t g_wk[(HIDDEN / 16) * (KV_DIM / 128) * 2048];
__device__ uint32_t g_wv[(HIDDEN / 16) * (KV_DIM / 128) * 2048];
__device__ uint32_t g_wo[(HIDDEN / 16) * (HIDDEN / 128) * 2048];
__device__ uint32_t g_oa[(SEQ / 128) * (HIDDEN / 16) * 2048];

// fragment-staged K/V for attention: [g(8)][tile(64)][2048 words]
__device__ uint32_t g_kf[N_KV * (SEQ / 32) * 2048];   // 4 MB
__device__ uint32_t g_vf[N_KV * (SEQ / 32) * 2048];   // 4 MB

__device__ __forceinline__ uint32_t f2tf32(float x) {
    uint32_t r;
    asm("cvt.rna.tf32.f32 %0, %1;" : "=r"(r) : "f"(x));
    return r;
}

__device__ __forceinline__ void mma_tf32(float c[4], const uint32_t a[4], const uint32_t b[2]) {
    asm volatile(
        "mma.sync.aligned.m16n8k8.row.col.f32.tf32.tf32.f32 "
        "{%0,%1,%2,%3},{%4,%5,%6,%7},{%8,%9},{%0,%1,%2,%3};"
        : "+f"(c[0]), "+f"(c[1]), "+f"(c[2]), "+f"(c[3])
        : "r"(a[0]), "r"(a[1]), "r"(a[2]), "r"(a[3]), "r"(b[0]), "r"(b[1]));
}

__device__ __forceinline__ uint32_t smem_u32(const void* p) {
    return (uint32_t)__cvta_generic_to_shared(p);
}
__device__ __forceinline__ void cp_async16(void* smem, const void* gmem) {
    asm volatile("cp.async.cg.shared.global [%0], [%1], 16;"
                 :: "r"(smem_u32(smem)), "l"(gmem));
}
#define CP_COMMIT() asm volatile("cp.async.commit_group;")
#define CP_WAIT2()  asm volatile("cp.async.wait_group 2;")

// ---------------- fragment scatter maps ------------------------------------
__device__ __forceinline__ void stage_a(uint32_t* dst, float4 v, int lin) {
    const int arow = lin >> 2;
    const int cbase = (lin & 3) * 4;
    float vv[4] = {v.x, v.y, v.z, v.w};
#pragma unroll
    for (int u = 0; u < 4; u++) {
        int j  = cbase + u;
        int mt = arow >> 4, rr = arow & 15;
        int ks = j >> 3,    cc = j & 7;
        int t   = (rr & 7) * 4 + (cc & 3);
        int reg = (rr >> 3) + 2 * (cc >> 2);
        dst[((mt * 2 + ks) * 32 + t) * 4 + reg] = f2tf32(vv[u]);
    }
}
__device__ __forceinline__ void stage_b(uint32_t* dst, float4 v, int lin) {
    const int brow = lin >> 5;
    const int cbase = (lin & 31) * 4;
    float vv[4] = {v.x, v.y, v.z, v.w};
#pragma unroll
    for (int u = 0; u < 4; u++) {
        int j  = cbase + u;
        int nt = j >> 3, cc = j & 7;
        int ks = brow >> 3, kk = brow & 7;
        int t   = cc * 4 + (kk & 3);
        int reg = kk >> 2;
        dst[((nt * 2 + ks) * 32 + t) * 2 + reg] = f2tf32(vv[u]);
    }
}

// ---------------- combined shuffle (all operands, one launch) ---------------
__device__ __forceinline__ void shuffle_a_body(
    const float* __restrict__ A, uint32_t* __restrict__ Af,
    int K, int ktp, int by, uint32_t* buf)
{
    const int kt0 = ktp * 2;
    const int Kt = K / 16;
    const int tid = threadIdx.x;
    const int row0 = tid >> 2, c40 = (tid & 3) * 4;
    const int lin1 = 256 + tid;
    const int row1 = lin1 >> 2, c41 = (lin1 & 3) * 4;
    const float* Ab = A + (size_t)(by * 128) * K;

    float4 v[2][2];
#pragma unroll
    for (int t = 0; t < 2; t++) {
        const float* base = Ab + (kt0 + t) * 16;
        v[t][0] = *(const float4*)(base + (size_t)row0 * K + c40);
        v[t][1] = *(const float4*)(base + (size_t)row1 * K + c41);
    }
#pragma unroll
    for (int t = 0; t < 2; t++) {
        stage_a(buf + t * 2048, v[t][0], tid);
        stage_a(buf + t * 2048, v[t][1], lin1);
    }
    __syncthreads();
#pragma unroll
    for (int t = 0; t < 2; t++) {
        uint32_t* dst = Af + ((size_t)by * Kt + kt0 + t) * 2048;
        *(uint4*)(dst + tid * 4)        = *(const uint4*)(buf + t * 2048 + tid * 4);
        *(uint4*)(dst + 1024 + tid * 4) = *(const uint4*)(buf + t * 2048 + 1024 + tid * 4);
    }
}

__device__ __forceinline__ void shuffle_b_body(
    const float* __restrict__ B, uint32_t* __restrict__ Bf,
    int K, int N, int bx, int ktp, uint32_t* buf)
{
    const int kt0 = ktp * 2;
    const int NB = N / 128;
    const int tid = threadIdx.x;
    const int brow0 = tid >> 5, c40 = (tid & 31) * 4;
    const int lin1 = 256 + tid;
    const int brow1 = lin1 >> 5, c41 = (lin1 & 31) * 4;

    float4 v[2][2];
#pragma unroll
    for (int t = 0; t < 2; t++) {
        const float* Bb = B + (size_t)((kt0 + t) * 16) * N + bx * 128;
        v[t][0] = *(const float4*)(Bb + (size_t)brow0 * N + c40);
        v[t][1] = *(const float4*)(Bb + (size_t)brow1 * N + c41);
    }
#pragma unroll
    for (int t = 0; t < 2; t++) {
        stage_b(buf + t * 2048, v[t][0], tid);
        stage_b(buf + t * 2048, v[t][1], lin1);
    }
    __syncthreads();
#pragma unroll
    for (int t = 0; t < 2; t++) {
        uint32_t* dst = Bf + ((size_t)(kt0 + t) * NB + bx) * 2048;
        *(uint4*)(dst + tid * 4)        = *(const uint4*)(buf + t * 2048 + tid * 4);
        *(uint4*)(dst + 1024 + tid * 4) = *(const uint4*)(buf + t * 2048 + 1024 + tid * 4);
    }
}

__global__ __launch_bounds__(256) void shuffle_all_kernel(
    const float* __restrict__ x,
    const float* __restrict__ Wq, const float* __restrict__ Wk,
    const float* __restrict__ Wv, const float* __restrict__ Wo,
    uint32_t* __restrict__ xa, uint32_t* __restrict__ wq,
    uint32_t* __restrict__ wk, uint32_t* __restrict__ wv,
    uint32_t* __restrict__ wo)
{
    __shared__ __align__(16) uint32_t buf[2 * 2048];
    int b = blockIdx.x;
    if (b < 1024) {
        shuffle_a_body(x, xa, HIDDEN, b & 63, b >> 6, buf);
    } else if (b < 2048) {
        b -= 1024;
        shuffle_b_body(Wq, wq, HIDDEN, HIDDEN, b & 15, b >> 4, buf);
    } else if (b < 2304) {
        b -= 2048;
        shuffle_b_body(Wk, wk, HIDDEN, KV_DIM, b & 3, b >> 2, buf);
    } else if (b < 2560) {
        b -= 2304;
        shuffle_b_body(Wv, wv, HIDDEN, KV_DIM, b & 3, b >> 2, buf);
    } else {
        b -= 2560;
        shuffle_b_body(Wo, wo, HIDDEN, HIDDEN, b & 15, b >> 4, buf);
    }
}

// ---------------- GEMM core: 128x256 tile, 4-stage cp.async -----------------
// Two adjacent N-tiles per CTA share one A tile: 12KB L2 traffic per
// 128x128x16 unit (vs 16KB) and contiguous 16KB B loads.
__device__ __forceinline__ void gemm_core2(
    const uint32_t* __restrict__ Abase,
    const uint32_t* __restrict__ Bf,
    int Kt, int NB, int bx2,
    const float* __restrict__ bias, float* __restrict__ C, int N,
    int by, uint32_t* As, uint32_t* Bs)
{
    const int tid  = threadIdx.x;
    const int lane = tid & 31;
    const int wid  = tid >> 5;
    const int warp_m = wid >> 2;     // 0..1 (64 rows each)
    const int warp_n = wid & 3;      // 0..3 (64 cols each of 256)
    const int bt  = warp_n >> 1;     // B buffer tile (0/1)
    const int nl0 = (warp_n & 1) * 8;  // first local n-subtile in that tile

    float c[4][8][4];
#pragma unroll
    for (int i = 0; i < 4; i++)
#pragma unroll
        for (int j = 0; j < 8; j++)
#pragma unroll
            for (int r = 0; r < 4; r++) c[i][j][r] = 0.f;

    const int ao0 = tid * 4;
    const int ao1 = 2048 + tid * 4;   // unused pattern guard
    (void)ao1;

#define G2_ISSUE(kt_, s_)                                                    \
    do {                                                                     \
        if ((kt_) < Kt) {                                                    \
            const uint32_t* ag = Abase + (size_t)(kt_) * 2048;               \
            const uint32_t* bg = Bf + ((size_t)(kt_) * NB + bx2 * 2) * 2048; \
            cp_async16(&As[(s_) * 2048 + ao0], ag + ao0);                    \
            cp_async16(&As[(s_) * 2048 + 1024 + tid * 4], ag + 1024 + tid * 4); \
            _Pragma("unroll")                                                \
            for (int j_ = 0; j_ < 4; j_++) {                                 \
                int off_ = j_ * 1024 + tid * 4;                              \
                cp_async16(&Bs[(s_) * 4096 + off_], bg + off_);              \
            }                                                                \
        }                                                                    \
        CP_COMMIT();                                                         \
    } while (0)

    G2_ISSUE(0, 0);
    G2_ISSUE(1, 1);
    G2_ISSUE(2, 2);

    for (int kt = 0; kt < Kt; kt++) {
        const int s = kt & 3;
        CP_WAIT2();
        __syncthreads();
        G2_ISSUE(kt + 3, (kt + 3) & 3);

        const uint32_t* Ass = &As[s * 2048];
        const uint32_t* Bss = &Bs[s * 4096 + bt * 2048];
#pragma unroll
        for (int ks = 0; ks < 2; ks++) {
            uint4 a[4];
            uint2 b[8];
#pragma unroll
            for (int mt = 0; mt < 4; mt++)
                a[mt] = *(const uint4*)&Ass[(((warp_m * 4 + mt) * 2 + ks) * 32 + lane) * 4];
#pragma unroll
            for (int j = 0; j < 8; j++)
                b[j] = *(const uint2*)&Bss[(((nl0 + j) * 2 + ks) * 32 + lane) * 2];
#pragma unroll
            for (int mt = 0; mt < 4; mt++)
#pragma unroll
                for (int j = 0; j < 8; j++) {
                    uint32_t ar[4] = {a[mt].x, a[mt].y, a[mt].z, a[mt].w};
                    uint32_t br[2] = {b[j].x, b[j].y};
                    mma_tf32(c[mt][j], ar, br);
                }
        }
    }
#undef G2_ISSUE

#pragma unroll
    for (int mt = 0; mt < 4; mt++) {
        int gr = by * 128 + warp_m * 64 + mt * 16 + (lane >> 2);
#pragma unroll
        for (int j = 0; j < 8; j++) {
            int gc = bx2 * 256 + bt * 128 + (nl0 + j) * 8 + (lane & 3) * 2;
            float b0 = bias[gc], b1 = bias[gc + 1];
            float2 r0 = {c[mt][j][0] + b0, c[mt][j][1] + b1};
            float2 r1 = {c[mt][j][2] + b0, c[mt][j][3] + b1};
            *(float2*)(C + (size_t)gr * N + gc) = r0;
            *(float2*)(C + (size_t)(gr + 8) * N + gc) = r1;
        }
    }
}

// fused Q/K/V: grid (12, 16); bx 0-7 -> Q pairs, 8-9 -> K pairs, 10-11 -> V
__global__ __launch_bounds__(256) void tf32_gemm_qkv(
    const uint32_t* __restrict__ Af,
    const uint32_t* __restrict__ Bq, const uint32_t* __restrict__ Bk,
    const uint32_t* __restrict__ Bv,
    const float* __restrict__ bq, const float* __restrict__ bk,
    const float* __restrict__ bv,
    float* __restrict__ cq, float* __restrict__ ck, float* __restrict__ cv)
{
    extern __shared__ __align__(16) uint32_t smem[];
    uint32_t* As = smem;               // 4 * 2048
    uint32_t* Bs = smem + 4 * 2048;    // 4 * 4096

    const int bx = blockIdx.x;
    const int by = blockIdx.y;
    const int Kt = HIDDEN / 16;

    const uint32_t* Bf;
    const float* bias;
    float* C;
    int N, NB, bx2;
    if (bx < 8)       { Bf = Bq; bias = bq; C = cq; N = HIDDEN; NB = 16; bx2 = bx; }
    else if (bx < 10) { Bf = Bk; bias = bk; C = ck; N = KV_DIM; NB = 4;  bx2 = bx - 8; }
    else              { Bf = Bv; bias = bv; C = cv; N = KV_DIM; NB = 4;  bx2 = bx - 10; }

    gemm_core2(Af + (size_t)by * Kt * 2048, Bf, Kt, NB, bx2, bias, C, N, by, As, Bs);
}

// generic staged GEMM (O projection): grid (N/256, M/128)
__global__ __launch_bounds__(256) void tf32_gemm_staged(
    const uint32_t* __restrict__ Af, const uint32_t* __restrict__ Bf,
    const float* __restrict__ bias, float* __restrict__ C,
    int M, int N, int K)
{
    extern __shared__ __align__(16) uint32_t smem[];
    uint32_t* As = smem;
    uint32_t* Bs = smem + 4 * 2048;
    const int Kt = K / 16;
    gemm_core2(Af + (size_t)blockIdx.y * Kt * 2048, Bf, Kt, N / 128, blockIdx.x,
               bias, C, N, blockIdx.y, As, Bs);
}

// ---------------- fused per-head LayerNorm + RoPE (q and k, one launch) -----
__global__ void ln_rope_all(float* __restrict__ qb_, float* __restrict__ kb_,
                            const float* __restrict__ q_g, const float* __restrict__ q_b,
                            const float* __restrict__ k_g, const float* __restrict__ k_b)
{
    int row = blockIdx.x * blockDim.y + threadIdx.y;
    const int QROWS = SEQ * N_HEADS;
    const int TOT = QROWS + SEQ * N_KV;
    if (row >= TOT) return;

    float* buf; const float* gamma; const float* beta; int heads; int lrow;
    if (row < QROWS) { buf = qb_; gamma = q_g; beta = q_b; heads = N_HEADS; lrow = row; }
    else             { buf = kb_; gamma = k_g; beta = k_b; heads = N_KV;   lrow = row - QROWS; }

    int s = lrow / heads;
    int lane = threadIdx.x;

    float* p = buf + (size_t)lrow * HEAD_DIM;
    float x0 = p[lane];
    float x1 = p[lane + 32];

    float sum = x0 + x1;
    float sq  = x0 * x0 + x1 * x1;
#pragma unroll
    for (int o = 16; o > 0; o >>= 1) {
        sum += __shfl_xor_sync(0xFFFFFFFFu, sum, o);
        sq  += __shfl_xor_sync(0xFFFFFFFFu, sq,  o);
    }
    float mean = sum * (1.0f / 64.0f);
    float var  = sq * (1.0f / 64.0f) - mean * mean;
    float inv  = rsqrtf(var + 1e-5f);

    float y0 = (x0 - mean) * inv * gamma[lane]      + beta[lane];
    float y1 = (x1 - mean) * inv * gamma[lane + 32] + beta[lane + 32];

    float freq = powf(10000.0f, -(float)lane * (1.0f / 32.0f));
    float ang  = (float)s * freq;
    float c, sn;
    sincosf(ang, &sn, &c);

    p[lane]      = y0 * c - y1 * sn;
    p[lane + 32] = y1 * c + y0 * sn;
}

// ---------------- K/V -> fragment layout conversion (once per launch) -------
__global__ __launch_bounds__(128) void kv_frag_kernel(
    const float* __restrict__ k, const float* __restrict__ v,
    uint32_t* __restrict__ kfrag, uint32_t* __restrict__ vfrag)
{
    __shared__ __align__(16) uint32_t buf[2048];
    const int t = blockIdx.x;
    const int g = blockIdx.y;
    const int which = blockIdx.z;
    const int tid = threadIdx.x;

    const float* src = (which == 0 ? k : v) + g * HEAD_DIM;
#pragma unroll
    for (int i = 0; i < 4; i++) {
        int f4 = tid + i * 128;
        int row = f4 >> 4, c4 = (f4 & 15) * 4;
        float4 val = *(const float4*)(src + (size_t)(t * 32 + row) * KV_DIM + c4);
        if (which == 0) {
            int ntb = row >> 3, gidb = row & 7;
            int ksb = c4 >> 3, regb = (c4 & 4) >> 2;
            uint32_t* kd = &buf[(ntb * 8 + ksb) * 64 + gidb * 8 + regb];
            kd[0] = f2tf32(val.x); kd[2] = f2tf32(val.y);
            kd[4] = f2tf32(val.z); kd[6] = f2tf32(val.w);
        } else {
            int kj = row >> 3, r8 = row & 7;
            int tigv = r8 & 3, regv = r8 >> 2;
            float vals[4] = {val.x, val.y, val.z, val.w};
#pragma unroll
            for (int u = 0; u < 4; u++) {
                int c = c4 + u;
                int ntv = c >> 3, gidv = c & 7;
                buf[(ntv * 4 + kj) * 64 + gidv * 8 + tigv * 2 + regv] = f2tf32(vals[u]);
            }
        }
    }
    __syncthreads();
    uint32_t* dst = (which == 0 ? kfrag : vfrag) + ((size_t)g * 64 + t) * 2048;
#pragma unroll
    for (int j = 0; j < 4; j++)
        *(uint4*)(dst + j * 512 + tid * 4) = *(const uint4*)(buf + j * 512 + tid * 4);
}

// ============================================================================
// Tensor-core flash attention (tf32 mma, non-causal, GQA)
// Static-shift softmax (post-LN rows have norm 8 -> |score|<=8).
// ============================================================================
#define AT_BK 32
#define SOFTMAX_SHIFT 24.0f
#define ATTN_SMEM_BYTES ((4 * 2048 * 2 + 4096) * 4)   // 80 KB

__global__ __launch_bounds__(128) void attn_mma_kernel(
    const float* __restrict__ q, const uint32_t* __restrict__ kfrag,
    const uint32_t* __restrict__ vfrag, uint32_t* __restrict__ o_frag)
{
    extern __shared__ __align__(16) uint32_t sm[];
    uint32_t* Kfs = sm;               // [4][2048]
    uint32_t* Vfs = sm + 4 * 2048;    // [4][2048]
    uint32_t* Pf  = sm + 8 * 2048;    // [8][512] A-frag

    const int h   = blockIdx.y;
    const int g   = h >> 2;
    const int q0  = blockIdx.x * 128;
    const int tid = threadIdx.x;
    const int w   = tid >> 5;      // 0..3
    const int lane = tid & 31;
    const int gid  = lane >> 2;
    const int tig  = lane & 3;

    // ---- Q fragments in registers ----
    uint32_t qf[2][8][4];
#pragma unroll
    for (int mt = 0; mt < 2; mt++) {
        const float* qp = q + (size_t)(q0 + w * 32 + mt * 16) * HIDDEN + h * HEAD_DIM;
#pragma unroll
        for (int ks = 0; ks < 8; ks++) {
            qf[mt][ks][0] = f2tf32(qp[(size_t)gid       * HIDDEN + ks * 8 + tig]);
            qf[mt][ks][1] = f2tf32(qp[(size_t)(gid + 8) * HIDDEN + ks * 8 + tig]);
            qf[mt][ks][2] = f2tf32(qp[(size_t)gid       * HIDDEN + ks * 8 + tig + 4]);
            qf[mt][ks][3] = f2tf32(qp[(size_t)(gid + 8) * HIDDEN + ks * 8 + tig + 4]);
        }
    }

    float o[2][8][4];
#pragma unroll
    for (int mt = 0; mt < 2; mt++)
#pragma unroll
        for (int nt = 0; nt < 8; nt++)
#pragma unroll
            for (int r = 0; r < 4; r++) o[mt][nt][r] = 0.f;
    float l[2][2] = {{0.f, 0.f}, {0.f, 0.f}};

    const uint32_t* kg = kfrag + (size_t)g * 64 * 2048;
    const uint32_t* vg = vfrag + (size_t)g * 64 * 2048;
    const int NT = SEQ / AT_BK;   // 64

#define A_ISSUE(t_, s_)                                                       \
    do {                                                                      \
        if ((t_) < NT) {                                                      \
            const uint32_t* kgp = kg + (size_t)(t_) * 2048;                   \
            const uint32_t* vgp = vg + (size_t)(t_) * 2048;                   \
            _Pragma("unroll")                                                 \
            for (int j_ = 0; j_ < 4; j_++) {                                  \
                int off_ = j_ * 512 + tid * 4;                                \
                cp_async16(&Kfs[(s_) * 2048 + off_], kgp + off_);             \
                cp_async16(&Vfs[(s_) * 2048 + off_], vgp + off_);             \
            }                                                                 \
        }                                                                     \
        CP_COMMIT();                                                          \
    } while (0)

    A_ISSUE(0, 0);
    A_ISSUE(1, 1);
    A_ISSUE(2, 2);

    const int r2  = 2 * (tig >> 1);
    const int ta0 = (2 * tig) & 3;
    const int ta1 = (2 * tig + 1) & 3;

    for (int t = 0; t < NT; t++) {
        const int s = t & 3;
        CP_WAIT2();
        __syncthreads();
        A_ISSUE(t + 3, (t + 3) & 3);

        const uint32_t* Ks = &Kfs[s * 2048];
        const uint32_t* Vs = &Vfs[s * 2048];

        // ---- QK^T ----
        float sc[2][4][4];
#pragma unroll
        for (int mt = 0; mt < 2; mt++)
#pragma unroll
            for (int nt = 0; nt < 4; nt++)
#pragma unroll
                for (int r = 0; r < 4; r++) sc[mt][nt][r] = 0.f;
#pragma unroll
        for (int ks = 0; ks < 8; ks++) {
#pragma unroll
            for (int nt = 0; nt < 4; nt++) {
                uint2 bb = *(const uint2*)&Ks[(nt * 8 + ks) * 64 + lane * 2];
                uint32_t br[2] = {bb.x, bb.y};
                mma_tf32(sc[0][nt], qf[0][ks], br);
                mma_tf32(sc[1][nt], qf[1][ks], br);
            }
        }

        // ---- static-shift softmax: p = exp(s/8 - SHIFT) ----
#pragma unroll
        for (int mt = 0; mt < 2; mt++) {
            uint32_t* Pw = &Pf[(w * 2 + mt) * 512];
#pragma unroll
            for (int nt = 0; nt < 4; nt++) {
                float p00 = __expf(fmaf(sc[mt][nt][0], 0.125f, -SOFTMAX_SHIFT));
                float p01 = __expf(fmaf(sc[mt][nt][1], 0.125f, -SOFTMAX_SHIFT));
                float p10 = __expf(fmaf(sc[mt][nt][2], 0.125f, -SOFTMAX_SHIFT));
                float p11 = __expf(fmaf(sc[mt][nt][3], 0.125f, -SOFTMAX_SHIFT));
                l[mt][0] += p00 + p01;
                l[mt][1] += p10 + p11;
                uint32_t* w0 = &Pw[(nt * 32 + gid * 4 + ta0) * 4 + r2];
                uint32_t* w1 = &Pw[(nt * 32 + gid * 4 + ta1) * 4 + r2];
                w0[0] = f2tf32(p00); w0[1] = f2tf32(p10);
                w1[0] = f2tf32(p01); w1[1] = f2tf32(p11);
            }
        }
        __syncwarp();

        // ---- O += P @ V ----
#pragma unroll
        for (int kj = 0; kj < 4; kj++) {
            uint4 pa0 = *(const uint4*)&Pf[(w * 2 + 0) * 512 + (kj * 32 + lane) * 4];
            uint4 pa1 = *(const uint4*)&Pf[(w * 2 + 1) * 512 + (kj * 32 + lane) * 4];
            uint32_t a0[4] = {pa0.x, pa0.y, pa0.z, pa0.w};
            uint32_t a1[4] = {pa1.x, pa1.y, pa1.z, pa1.w};
#pragma unroll
            for (int nt = 0; nt < 8; nt++) {
                uint2 bb = *(const uint2*)&Vs[(nt * 4 + kj) * 64 + lane * 2];
                uint32_t br[2] = {bb.x, bb.y};
                mma_tf32(o[0][nt], a0, br);
                mma_tf32(o[1][nt], a1, br);
            }
        }
    }
#undef A_ISSUE

    // ---- reduce l across the quad (once) ----
#pragma unroll
    for (int mt = 0; mt < 2; mt++) {
        l[mt][0] += __shfl_xor_sync(0xFFFFFFFFu, l[mt][0], 1);
        l[mt][0] += __shfl_xor_sync(0xFFFFFFFFu, l[mt][0], 2);
        l[mt][1] += __shfl_xor_sync(0xFFFFFFFFu, l[mt][1], 1);
        l[mt][1] += __shfl_xor_sync(0xFFFFFFFFu, l[mt][1], 2);
    }

    // ---- write O directly into A-fragment layout for the Wo GEMM ----
    const int Kt = HIDDEN / 16;
    const int by = q0 >> 7;
    uint32_t* dstb = o_frag + (size_t)by * Kt * 2048;
    const int cc0 = 2 * tig;
    const int rhi = cc0 >> 2;
    const int t0 = gid * 4 + (cc0 & 3);
    const int t1 = gid * 4 + ((cc0 + 1) & 3);
#pragma unroll
    for (int mt = 0; mt < 2; mt++) {
        const float il0 = 1.0f / l[mt][0], il1 = 1.0f / l[mt][1];
        const int mt_g = w * 2 + mt;
#pragma unroll
        for (int nt = 0; nt < 8; nt++) {
            int kt = h * 4 + (nt >> 1);
            int ks = nt & 1;
            uint32_t* base = dstb + (size_t)kt * 2048 + (size_t)((mt_g * 2 + ks) * 32) * 4;
            base[t0 * 4 + 2 * rhi]     = f2tf32(o[mt][nt][0] * il0);
            base[t1 * 4 + 2 * rhi]     = f2tf32(o[mt][nt][1] * il0);
            base[t0 * 4 + 1 + 2 * rhi] = f2tf32(o[mt][nt][2] * il1);
            base[t1 * 4 + 1 + 2 * rhi] = f2tf32(o[mt][nt][3] * il1);
        }
    }
}

// ---------------- launch --------------------------------------------------
extern "C" void kernel_launch(void* const* d_in, const int* in_sizes, int n_in,
                              void* d_out, int out_size)
{
    const float* x   = (const float*)d_in[0];
    const float* Wq  = (const float*)d_in[1];
    const float* bq  = (const float*)d_in[2];
    const float* Wk  = (const float*)d_in[3];
    const float* bk  = (const float*)d_in[4];
    const float* Wv  = (const float*)d_in[5];
    const float* bv  = (const float*)d_in[6];
    const float* Wo  = (const float*)d_in[7];
    const float* bo  = (const float*)d_in[8];
    const float* q_g = (const float*)d_in[9];
    const float* q_b = (const float*)d_in[10];
    const float* k_g = (const float*)d_in[11];
    const float* k_b = (const float*)d_in[12];
    float* out = (float*)d_out;

    void *pq, *pk, *pv;
    void *pxa, *pwq, *pwk, *pwv, *pwo, *poa, *pkf, *pvf;
    cudaGetSymbolAddress(&pq, g_q);
    cudaGetSymbolAddress(&pk, g_k);
    cudaGetSymbolAddress(&pv, g_v);
    cudaGetSymbolAddress(&pxa, g_xa);
    cudaGetSymbolAddress(&pwq, g_wq);
    cudaGetSymbolAddress(&pwk, g_wk);
    cudaGetSymbolAddress(&pwv, g_wv);
    cudaGetSymbolAddress(&pwo, g_wo);
    cudaGetSymbolAddress(&poa, g_oa);
    cudaGetSymbolAddress(&pkf, g_kf);
    cudaGetSymbolAddress(&pvf, g_vf);
    float* fq = (float*)pq;
    float* fk = (float*)pk;
    float* fv = (float*)pv;
    uint32_t* xa = (uint32_t*)pxa;
    uint32_t* wqf = (uint32_t*)pwq;
    uint32_t* wkf = (uint32_t*)pwk;
    uint32_t* wvf = (uint32_t*)pwv;
    uint32_t* wof = (uint32_t*)pwo;
    uint32_t* oa = (uint32_t*)poa;
    uint32_t* kfr = (uint32_t*)pkf;
    uint32_t* vfr = (uint32_t*)pvf;

    const int GEMM_SMEM = (4 * 2048 + 4 * 4096) * 4;   // 96 KB
    cudaFuncSetAttribute(tf32_gemm_qkv,
                         cudaFuncAttributeMaxDynamicSharedMemorySize, GEMM_SMEM);
    cudaFuncSetAttribute(tf32_gemm_staged,
                         cudaFuncAttributeMaxDynamicSharedMemorySize, GEMM_SMEM);
    cudaFuncSetAttribute(attn_mma_kernel,
                         cudaFuncAttributeMaxDynamicSharedMemorySize, ATTN_SMEM_BYTES);

    // one combined shuffle launch (x + all 4 weights)
    shuffle_all_kernel<<<3584, 256>>>(x, Wq, Wk, Wv, Wo, xa, wqf, wkf, wvf, wof);

    // fused Q/K/V projections (128x256 tiles)
    {
        dim3 grid(12, SEQ / 128);
        tf32_gemm_qkv<<<grid, 256, GEMM_SMEM>>>(xa, wqf, wkf, wvf,
                                                bq, bk, bv, fq, fk, fv);
    }

    // per-head LN + RoPE (q and k in one launch)
    {
        dim3 blk(32, 4);
        int rows = SEQ * N_HEADS + SEQ * N_KV;
        ln_rope_all<<<(rows + 3) / 4, blk>>>(fq, fk, q_g, q_b, k_g, k_b);
    }

    // K/V -> fragment layout (once)
    {
        dim3 grid(SEQ / 32, N_KV, 2);
        kv_frag_kernel<<<grid, 128>>>(fk, fv, kfr, vfr);
    }

    // attention (BQ=128, 4 warps x m32, static-shift softmax)
    {
        dim3 grid(SEQ / 128, N_HEADS);
        attn_mma_kernel<<<grid, 128, ATTN_SMEM_BYTES>>>(fq, kfr, vfr, oa);
    }

    // output projection (128x256 tiles)
    {
        dim3 grid(HIDDEN / 256, SEQ / 128);
        tf32_gemm_staged<<<grid, 256, GEMM_SMEM>>>(oa, wof, bo, out, SEQ, HIDDEN, HIDDEN);
    }
}